// round 5
// baseline (speedup 1.0000x reference)
#include <cuda_runtime.h>
#include <cuda_bf16.h>
#include <math.h>
#include <stdint.h>

#define Dn 4096
#define Bn 32
#define Un 64

__device__ __nv_bfloat16 g_xsp[2][64][Dn];  // rows 0-31 hi(X), 32-63 lo(X)
__device__ float g_act[2][Bn * Dn];
__device__ float g_mp1[32][Bn][512];
__device__ float g_mp2[8][Bn][256];
__device__ float g_mp3[8][Bn][64];
__device__ float g_h1[Bn * 512];
__device__ float g_h2[Bn * 256];
__device__ float g_o[Bn * Un];
__device__ float g_alpha[Dn];
__device__ float g_norm[2][Dn];
__device__ float g_part[2][64][Dn];

#define PACK2(v, lo, hi) asm("mov.b64 %0, {%1, %2};" : "=l"(v) : "f"(lo), "f"(hi))
#define UNPK2(lo, hi, v) asm("mov.b64 {%0, %1}, %2;" : "=f"(lo), "=f"(hi) : "l"(v))
#define FMA2(d, a, b) asm("fma.rn.f32x2 %0, %1, %2, %0;" : "+l"(d) : "l"(a), "l"(b))

__device__ __forceinline__ uint32_t smem_u32(const void* p) {
    uint32_t a;
    asm("{ .reg .u64 t; cvta.to.shared.u64 t, %1; cvt.u32.u64 %0, t; }" : "=r"(a) : "l"(p));
    return a;
}
__device__ __forceinline__ uint32_t pack_hi(float f0, float f1) {
    return (uint32_t)__bfloat16_as_ushort(__float2bfloat16(f0))
         | ((uint32_t)__bfloat16_as_ushort(__float2bfloat16(f1)) << 16);
}
__device__ __forceinline__ uint32_t pack_lo(float f0, float f1) {
    float r0 = f0 - __bfloat162float(__float2bfloat16(f0));
    float r1 = f1 - __bfloat162float(__float2bfloat16(f1));
    return pack_hi(r0, r1);
}
__device__ __forceinline__ void mma16816(float* d, uint32_t a0, uint32_t a1,
                                         uint32_t a2, uint32_t a3,
                                         uint32_t b0, uint32_t b1) {
    asm volatile(
        "mma.sync.aligned.m16n8k16.row.col.f32.bf16.bf16.f32 "
        "{%0,%1,%2,%3}, {%4,%5,%6,%7}, {%8,%9}, {%0,%1,%2,%3};"
        : "+f"(d[0]), "+f"(d[1]), "+f"(d[2]), "+f"(d[3])
        : "r"(a0), "r"(a1), "r"(a2), "r"(a3), "r"(b0), "r"(b1));
}

// ---------------------------------------------------------------------------
__global__ __launch_bounds__(256) void prep_x(const float* __restrict__ stim,
                                              const float* __restrict__ prev)
{
    int mat = blockIdx.y;
    const float* X = mat ? prev : stim;
    int idx = blockIdx.x * 256 + threadIdx.x;
    float x = X[idx];
    __nv_bfloat16 hi = __float2bfloat16(x);
    __nv_bfloat16 lo = __float2bfloat16(x - __bfloat162float(hi));
    int b = idx >> 12, d = idx & 4095;
    g_xsp[mat][b][d] = hi;
    g_xsp[mat][b + 32][d] = lo;
}

// ---------------------------------------------------------------------------
// fwd via mma.sync bf16 hi/lo split. Per CTA: one (mat, 64-wide n tile).
// M=64 ([hi(X);lo(X)]), warp w owns 8 columns. D += A@Bhi + A@Blo;
// epilogue: row r + row r+32, relu, store to g_act.
// ---------------------------------------------------------------------------
__global__ __launch_bounds__(256) void fwd_mma(
    const float* __restrict__ Wh, const float* __restrict__ Wr)
{
    const int mat = blockIdx.y;
    const float* __restrict__ W = mat ? Wr : Wh;
    const int n0 = blockIdx.x * 64;

    __shared__ __nv_bfloat16 As[64][72];   // row stride 144B -> LDSM conflict-free

    const int tid  = threadIdx.x;
    const int lane = tid & 31;
    const int wid  = tid >> 5;
    const int nw   = n0 + wid * 8;
    const int bn   = lane >> 2;            // B column within warp tile
    const int bk   = (lane & 3) * 2;       // B k-pair base
    const float* __restrict__ Wc = W + nw + bn;

    // ldmatrix source row/col for this lane (per m-tile, per k-step)
    const int lsub = lane >> 3;            // 0..3 submatrix
    const int lrow = (lane & 7) + ((lsub & 1) << 3);
    const int lcol = (lsub & 2) << 2;      // 0 or 8

    float d[4][4] = {};

    for (int s = 0; s < 64; ++s) {
        const int k0 = s * 64;
        {
            int c = tid;
            #pragma unroll
            for (int r = 0; r < 2; ++r, c += 256) {
                int row = c >> 3, ch = c & 7;
                *(uint4*)&As[row][ch * 8] = *(const uint4*)&g_xsp[mat][row][k0 + ch * 8];
            }
        }
        __syncthreads();
        #pragma unroll
        for (int kk = 0; kk < 4; ++kk) {
            const int kb = k0 + kk * 16 + bk;
            float f0 = Wc[(size_t)kb * Dn];
            float f1 = Wc[(size_t)(kb + 1) * Dn];
            float f2 = Wc[(size_t)(kb + 8) * Dn];
            float f3 = Wc[(size_t)(kb + 9) * Dn];
            uint32_t bh0 = pack_hi(f0, f1), bh1 = pack_hi(f2, f3);
            uint32_t bl0 = pack_lo(f0, f1), bl1 = pack_lo(f2, f3);
            #pragma unroll
            for (int mt = 0; mt < 4; ++mt) {
                uint32_t a0, a1, a2, a3;
                uint32_t sa = smem_u32(&As[mt * 16 + lrow][kk * 16 + lcol]);
                asm volatile(
                    "ldmatrix.sync.aligned.m8n8.x4.shared.b16 {%0,%1,%2,%3}, [%4];"
                    : "=r"(a0), "=r"(a1), "=r"(a2), "=r"(a3) : "r"(sa));
                mma16816(d[mt], a0, a1, a2, a3, bh0, bh1);
                mma16816(d[mt], a0, a1, a2, a3, bl0, bl1);
            }
        }
        __syncthreads();
    }

    // epilogue: rows r (hi) + r+32 (lo), relu, store
    const int g  = lane >> 2;
    const int cc = (lane & 3) * 2;
    #pragma unroll
    for (int h = 0; h < 2; ++h) {
        float v0 = d[h][0] + d[h + 2][0];
        float v1 = d[h][1] + d[h + 2][1];
        float v2 = d[h][2] + d[h + 2][2];
        float v3 = d[h][3] + d[h + 2][3];
        int r0 = h * 16 + g, r1 = r0 + 8;
        float2 p0 = {fmaxf(v0, 0.f), fmaxf(v1, 0.f)};
        float2 p1 = {fmaxf(v2, 0.f), fmaxf(v3, 0.f)};
        *(float2*)&g_act[mat][r0 * Dn + nw + cc] = p0;
        *(float2*)&g_act[mat][r1 * Dn + nw + cc] = p1;
    }
}

// ---------------------------------------------------------------------------
__global__ __launch_bounds__(256) void ln_final_kernel(
    const float* __restrict__ gamma, const float* __restrict__ beta,
    float* __restrict__ out)
{
    const int row = blockIdx.x;
    const float* rec = g_act[1] + row * Dn;
    const float* stm = g_act[0] + row * Dn;
    float s = 0.f, ss = 0.f;
    for (int i = threadIdx.x; i < Dn; i += 256) {
        float v = rec[i]; s += v; ss += v * v;
    }
    __shared__ float rs[256], rq[256];
    rs[threadIdx.x] = s; rq[threadIdx.x] = ss;
    __syncthreads();
    for (int off = 128; off > 0; off >>= 1) {
        if (threadIdx.x < off) {
            rs[threadIdx.x] += rs[threadIdx.x + off];
            rq[threadIdx.x] += rq[threadIdx.x + off];
        }
        __syncthreads();
    }
    float mean = rs[0] * (1.f / Dn);
    float var  = rq[0] * (1.f / Dn) - mean * mean;
    float inv  = rsqrtf(var + 1e-5f);
    for (int i = threadIdx.x; i < Dn; i += 256)
        out[row * Dn + i] = (rec[i] - mean) * inv * gamma[i] + beta[i] + stm[i];
}

// ---------------------------------------------------------------------------
__global__ __launch_bounds__(256) void mlp_gemm2(
    const float* __restrict__ xext, int insel,
    const float* __restrict__ W, int K, int N, int Kc, int psel)
{
    const float* __restrict__ X = (insel == 0) ? xext : g_h1;
    float* __restrict__ P = (psel == 1) ? &g_mp1[0][0][0] : &g_mp2[0][0][0];
    const int n0 = blockIdx.x * 128;
    const int kbase = blockIdx.y * Kc;
    const int iters = Kc >> 5;

    __shared__ float Xs[32][36];
    __shared__ float Ws[32][128];
    const int tid = threadIdx.x;
    const int xrow = tid >> 3, xk = (tid & 7) << 2;
    const int wk = tid >> 5, wn = (tid & 31) << 2;
    const int tx = tid & 31, ty = tid >> 5;

    float4 xr  = *(const float4*)&X[xrow * K + kbase + xk];
    float4 wr0 = *(const float4*)&W[(size_t)(kbase + wk +  0) * N + n0 + wn];
    float4 wr1 = *(const float4*)&W[(size_t)(kbase + wk +  8) * N + n0 + wn];
    float4 wr2 = *(const float4*)&W[(size_t)(kbase + wk + 16) * N + n0 + wn];
    float4 wr3 = *(const float4*)&W[(size_t)(kbase + wk + 24) * N + n0 + wn];
    float acc[4][4] = {};

    for (int c = 0; c < iters; ++c) {
        Xs[xk + 0][xrow] = xr.x; Xs[xk + 1][xrow] = xr.y;
        Xs[xk + 2][xrow] = xr.z; Xs[xk + 3][xrow] = xr.w;
        *(float4*)&Ws[wk +  0][wn] = wr0;
        *(float4*)&Ws[wk +  8][wn] = wr1;
        *(float4*)&Ws[wk + 16][wn] = wr2;
        *(float4*)&Ws[wk + 24][wn] = wr3;
        __syncthreads();
        if (c + 1 < iters) {
            int k = kbase + (c + 1) * 32;
            xr  = *(const float4*)&X[xrow * K + k + xk];
            wr0 = *(const float4*)&W[(size_t)(k + wk +  0) * N + n0 + wn];
            wr1 = *(const float4*)&W[(size_t)(k + wk +  8) * N + n0 + wn];
            wr2 = *(const float4*)&W[(size_t)(k + wk + 16) * N + n0 + wn];
            wr3 = *(const float4*)&W[(size_t)(k + wk + 24) * N + n0 + wn];
        }
        #pragma unroll 8
        for (int kk = 0; kk < 32; ++kk) {
            float4 a = *(const float4*)&Xs[kk][ty << 2];
            float4 b = *(const float4*)&Ws[kk][tx << 2];
            acc[0][0] = fmaf(a.x, b.x, acc[0][0]); acc[0][1] = fmaf(a.x, b.y, acc[0][1]);
            acc[0][2] = fmaf(a.x, b.z, acc[0][2]); acc[0][3] = fmaf(a.x, b.w, acc[0][3]);
            acc[1][0] = fmaf(a.y, b.x, acc[1][0]); acc[1][1] = fmaf(a.y, b.y, acc[1][1]);
            acc[1][2] = fmaf(a.y, b.z, acc[1][2]); acc[1][3] = fmaf(a.y, b.w, acc[1][3]);
            acc[2][0] = fmaf(a.z, b.x, acc[2][0]); acc[2][1] = fmaf(a.z, b.y, acc[2][1]);
            acc[2][2] = fmaf(a.z, b.z, acc[2][2]); acc[2][3] = fmaf(a.z, b.w, acc[2][3]);
            acc[3][0] = fmaf(a.w, b.x, acc[3][0]); acc[3][1] = fmaf(a.w, b.y, acc[3][1]);
            acc[3][2] = fmaf(a.w, b.z, acc[3][2]); acc[3][3] = fmaf(a.w, b.w, acc[3][3]);
        }
        __syncthreads();
    }
    #pragma unroll
    for (int m = 0; m < 4; ++m) {
        int row = (ty << 2) + m;
        float4 v = make_float4(acc[m][0], acc[m][1], acc[m][2], acc[m][3]);
        *(float4*)&P[((size_t)blockIdx.y * Bn + row) * N + n0 + (tx << 2)] = v;
    }
}

// ---------------------------------------------------------------------------
__global__ __launch_bounds__(256) void fc3_gemm(const float* __restrict__ W)
{
    const int kb = blockIdx.x * 32;
    __shared__ float Xs[32][33];
    __shared__ float Ws[32][64];
    const int tid = threadIdx.x;
    const int xrow = tid >> 3, xk = (tid & 7) << 2;
    const int kw = tid >> 4, wn = (tid & 15) << 2;

    float4 xv = *(const float4*)&g_h2[xrow * 256 + kb + xk];
    Xs[xk + 0][xrow] = xv.x; Xs[xk + 1][xrow] = xv.y;
    Xs[xk + 2][xrow] = xv.z; Xs[xk + 3][xrow] = xv.w;
    *(float4*)&Ws[kw +  0][wn] = *(const float4*)&W[(kb + kw +  0) * 64 + wn];
    *(float4*)&Ws[kw + 16][wn] = *(const float4*)&W[(kb + kw + 16) * 64 + wn];
    __syncthreads();

    const int tx = tid & 15, ty = tid >> 4;
    float acc[2][4] = {};
    #pragma unroll 8
    for (int kk = 0; kk < 32; ++kk) {
        float a0 = Xs[kk][ty * 2 + 0], a1 = Xs[kk][ty * 2 + 1];
        float4 b = *(const float4*)&Ws[kk][tx << 2];
        acc[0][0] = fmaf(a0, b.x, acc[0][0]); acc[0][1] = fmaf(a0, b.y, acc[0][1]);
        acc[0][2] = fmaf(a0, b.z, acc[0][2]); acc[0][3] = fmaf(a0, b.w, acc[0][3]);
        acc[1][0] = fmaf(a1, b.x, acc[1][0]); acc[1][1] = fmaf(a1, b.y, acc[1][1]);
        acc[1][2] = fmaf(a1, b.z, acc[1][2]); acc[1][3] = fmaf(a1, b.w, acc[1][3]);
    }
    #pragma unroll
    for (int m = 0; m < 2; ++m) {
        int row = ty * 2 + m;
        float4 v = make_float4(acc[m][0], acc[m][1], acc[m][2], acc[m][3]);
        *(float4*)&g_mp3[blockIdx.x][row][tx << 2] = v;
    }
}

// ---------------------------------------------------------------------------
__global__ __launch_bounds__(256) void lnact_reduce(
    int psel, int S, int N, const float* __restrict__ bias,
    const float* __restrict__ gamma, const float* __restrict__ beta, int act)
{
    const float* part = (psel == 1) ? &g_mp1[0][0][0]
                      : (psel == 2) ? &g_mp2[0][0][0] : &g_mp3[0][0][0];
    float* outb = (psel == 1) ? g_h1 : (psel == 2) ? g_h2 : g_o;
    const int row = blockIdx.x;
    __shared__ float vbuf[512];
    float s = 0.f, ss = 0.f;
    for (int i = threadIdx.x; i < N; i += 256) {
        float v = bias[i];
        for (int sp = 0; sp < S; ++sp)
            v += part[((size_t)sp * Bn + row) * N + i];
        vbuf[i] = v; s += v; ss += v * v;
    }
    __shared__ float rs[256], rq[256];
    rs[threadIdx.x] = s; rq[threadIdx.x] = ss;
    __syncthreads();
    for (int off = 128; off > 0; off >>= 1) {
        if (threadIdx.x < off) {
            rs[threadIdx.x] += rs[threadIdx.x + off];
            rq[threadIdx.x] += rq[threadIdx.x + off];
        }
        __syncthreads();
    }
    float mean = rs[0] / (float)N;
    float var  = rq[0] / (float)N - mean * mean;
    float inv  = rsqrtf(var + 1e-5f);
    for (int i = threadIdx.x; i < N; i += 256) {
        float v = (vbuf[i] - mean) * inv * gamma[i] + beta[i];
        outb[row * N + i] = (act == 1) ? fmaxf(v, 0.f) : tanhf(v);
    }
}

// ---------------------------------------------------------------------------
__global__ __launch_bounds__(256) void alpha_kernel()
{
    __shared__ float dsh[Un];
    int t = threadIdx.x;
    if (t < Un) {
        float s = 0.f;
        #pragma unroll
        for (int b = 0; b < Bn; b++) s += g_o[b * Un + t];
        dsh[t] = s * (9.9f / (float)Bn);
    }
    __syncthreads();
    for (int d = t; d < Dn; d += 256) g_alpha[d] = dsh[d >> 6];
}

// ---------------------------------------------------------------------------
__global__ __launch_bounds__(256) void update_kernel(
    const float* __restrict__ stim, const float* __restrict__ prev,
    const float* __restrict__ Wh, const float* __restrict__ Wr,
    const float* __restrict__ decay, float* __restrict__ out)
{
    const int mat = blockIdx.z;
    const float* __restrict__ A = mat ? prev : stim;
    const float* __restrict__ C = g_act[mat];
    const float* __restrict__ W = mat ? Wr : Wh;
    float* __restrict__ O = out + (size_t)(Bn + mat * Dn) * Dn;
    const int i0 = blockIdx.y * 64;
    const int j0 = blockIdx.x * 64;

    __shared__ float As[32][64];
    __shared__ float Cs[32][64];
    __shared__ float red[64][17];

    const int tid = threadIdx.x;
    for (int idx = tid; idx < 32 * 64; idx += 256) {
        int b = idx >> 6, c = idx & 63;
        As[b][c] = A[b * Dn + i0 + c];
        Cs[b][c] = C[b * Dn + j0 + c];
    }
    __syncthreads();

    const int tx = tid & 15, ty = tid >> 4;
    unsigned long long acc2[4][2] = {};
    #pragma unroll
    for (int b = 0; b < 32; b++) {
        float4 a4 = *(const float4*)&As[b][ty * 4];
        ulonglong2 c2 = *(const ulonglong2*)&Cs[b][tx * 4];
        unsigned long long am;
        PACK2(am, a4.x, a4.x); FMA2(acc2[0][0], am, c2.x); FMA2(acc2[0][1], am, c2.y);
        PACK2(am, a4.y, a4.y); FMA2(acc2[1][0], am, c2.x); FMA2(acc2[1][1], am, c2.y);
        PACK2(am, a4.z, a4.z); FMA2(acc2[2][0], am, c2.x); FMA2(acc2[2][1], am, c2.y);
        PACK2(am, a4.w, a4.w); FMA2(acc2[3][0], am, c2.x); FMA2(acc2[3][1], am, c2.y);
    }

    float4 al = *(const float4*)&g_alpha[j0 + tx * 4];
    float alv[4] = {al.x, al.y, al.z, al.w};
    #pragma unroll
    for (int m = 0; m < 4; m++) {
        int i = i0 + ty * 4 + m;
        float dm = 1.0f - decay[i];
        float4 w4 = *(const float4*)&W[(size_t)i * Dn + j0 + tx * 4];
        float wv[4] = {w4.x, w4.y, w4.z, w4.w};
        float ac[4];
        UNPK2(ac[0], ac[1], acc2[m][0]);
        UNPK2(ac[2], ac[3], acc2[m][1]);
        float v[4], ssum = 0.f;
        #pragma unroll
        for (int n = 0; n < 4; n++) {
            v[n] = (wv[n] + ac[n] * alv[n]) * dm;
            ssum = fmaf(v[n], v[n], ssum);
        }
        float4 o4 = {v[0], v[1], v[2], v[3]};
        *(float4*)&O[(size_t)i * Dn + j0 + tx * 4] = o4;
        red[ty * 4 + m][tx] = ssum;
    }
    __syncthreads();
    if (tid < 64) {
        float s = 0.f;
        #pragma unroll
        for (int t = 0; t < 16; t++) s += red[tid][t];
        g_part[mat][blockIdx.x][i0 + tid] = s;
    }
}

// ---------------------------------------------------------------------------
__global__ __launch_bounds__(256) void norm_reduce_kernel()
{
    int mat = blockIdx.y;
    int i = blockIdx.x * 256 + threadIdx.x;
    float s = 0.f;
    #pragma unroll 8
    for (int jb = 0; jb < 64; jb++) s += g_part[mat][jb][i];
    g_norm[mat][i] = s;
}

// ---------------------------------------------------------------------------
__global__ __launch_bounds__(256) void scale_kernel(float* __restrict__ out)
{
    float4* base = (float4*)(out + (size_t)Bn * Dn);
    int t0 = blockIdx.x * 1024 + threadIdx.x;
    #pragma unroll
    for (int r = 0; r < 4; r++) {
        int idx = t0 + r * 256;
        size_t e = (size_t)idx << 2;
        int mat = (int)(e >> 24);
        int i = (int)((e >> 12) & (Dn - 1));
        float sc = 1.0f / fmaxf(sqrtf(g_norm[mat][i]), 1e-12f);
        float4 v = base[idx];
        v.x *= sc; v.y *= sc; v.z *= sc; v.w *= sc;
        base[idx] = v;
    }
}

// ---------------------------------------------------------------------------
extern "C" void kernel_launch(void* const* d_in, const int* in_sizes, int n_in,
                              void* d_out, int out_size)
{
    const float* stimulus = (const float*)d_in[0];
    const float* prev_act = (const float*)d_in[1];
    const float* W_heb    = (const float*)d_in[2];
    const float* W_rec    = (const float*)d_in[3];
    const float* decay    = (const float*)d_in[4];
    const float* ln_rec_g = (const float*)d_in[5];
    const float* ln_rec_b = (const float*)d_in[6];
    const float* fc1_w    = (const float*)d_in[7];
    const float* fc1_b    = (const float*)d_in[8];
    const float* ln1_g    = (const float*)d_in[9];
    const float* ln1_b    = (const float*)d_in[10];
    const float* fc2_w    = (const float*)d_in[11];
    const float* fc2_b    = (const float*)d_in[12];
    const float* ln2_g    = (const float*)d_in[13];
    const float* ln2_b    = (const float*)d_in[14];
    const float* fc3_w    = (const float*)d_in[15];
    const float* fc3_b    = (const float*)d_in[16];
    const float* lno_g    = (const float*)d_in[17];
    const float* lno_b    = (const float*)d_in[18];
    float* out = (float*)d_out;

    prep_x<<<dim3(512, 2), 256>>>(stimulus, prev_act);
    fwd_mma<<<dim3(64, 2), 256>>>(W_heb, W_rec);
    ln_final_kernel<<<32, 256>>>(ln_rec_g, ln_rec_b, out);
    mlp_gemm2<<<dim3(4, 32), 256>>>(out, 0, fc1_w, 4096, 512, 128, 1);
    lnact_reduce<<<32, 256>>>(1, 32, 512, fc1_b, ln1_g, ln1_b, 1);
    mlp_gemm2<<<dim3(2, 8), 256>>>(nullptr, 1, fc2_w, 512, 256, 64, 2);
    lnact_reduce<<<32, 256>>>(2, 8, 256, fc2_b, ln2_g, ln2_b, 1);
    fc3_gemm<<<8, 256>>>(fc3_w);
    lnact_reduce<<<32, 256>>>(3, 8, 64, fc3_b, lno_g, lno_b, 2);
    alpha_kernel<<<1, 256>>>();
    update_kernel<<<dim3(64, 64, 2), 256>>>(stimulus, prev_act, W_heb, W_rec, decay, out);
    norm_reduce_kernel<<<dim3(16, 2), 256>>>();
    scale_kernel<<<8192, 256>>>(out);
}

// round 6
// speedup vs baseline: 1.6063x; 1.6063x over previous
#include <cuda_runtime.h>
#include <cuda_bf16.h>
#include <math.h>
#include <stdint.h>

#define Dn 4096
#define Bn 32
#define Un 64

__device__ __nv_bfloat16 g_xsp[2][64][Dn];  // rows 0-31 hi(X), 32-63 lo(X)
__device__ float g_fpart[4][2][Bn][Dn];     // fwd split-K partials
__device__ float g_act[2][Bn * Dn];
__device__ float g_mp1[32][Bn][512];
__device__ float g_mp2[8][Bn][256];
__device__ float g_mp3[8][Bn][64];
__device__ float g_h1[Bn * 512];
__device__ float g_h2[Bn * 256];
__device__ float g_o[Bn * Un];
__device__ float g_alpha[Dn];
__device__ float g_norm[2][Dn];
__device__ float g_part[2][64][Dn];

#define PACK2(v, lo, hi) asm("mov.b64 %0, {%1, %2};" : "=l"(v) : "f"(lo), "f"(hi))
#define UNPK2(lo, hi, v) asm("mov.b64 {%0, %1}, %2;" : "=f"(lo), "=f"(hi) : "l"(v))
#define FMA2(d, a, b) asm("fma.rn.f32x2 %0, %1, %2, %0;" : "+l"(d) : "l"(a), "l"(b))

__device__ __forceinline__ uint32_t smem_u32(const void* p) {
    uint32_t a;
    asm("{ .reg .u64 t; cvta.to.shared.u64 t, %1; cvt.u32.u64 %0, t; }" : "=r"(a) : "l"(p));
    return a;
}
__device__ __forceinline__ uint32_t pack_hi(float f0, float f1) {
    return (uint32_t)__bfloat16_as_ushort(__float2bfloat16(f0))
         | ((uint32_t)__bfloat16_as_ushort(__float2bfloat16(f1)) << 16);
}
__device__ __forceinline__ uint32_t pack_lo(float f0, float f1) {
    float r0 = f0 - __bfloat162float(__float2bfloat16(f0));
    float r1 = f1 - __bfloat162float(__float2bfloat16(f1));
    return pack_hi(r0, r1);
}
__device__ __forceinline__ void mma16816(float* d, const uint32_t* a,
                                         uint32_t b0, uint32_t b1) {
    asm volatile(
        "mma.sync.aligned.m16n8k16.row.col.f32.bf16.bf16.f32 "
        "{%0,%1,%2,%3}, {%4,%5,%6,%7}, {%8,%9}, {%0,%1,%2,%3};"
        : "+f"(d[0]), "+f"(d[1]), "+f"(d[2]), "+f"(d[3])
        : "r"(a[0]), "r"(a[1]), "r"(a[2]), "r"(a[3]), "r"(b0), "r"(b1));
}
#define LDSM_X4(r, p) \
    asm volatile("ldmatrix.sync.aligned.m8n8.x4.shared.b16 {%0,%1,%2,%3}, [%4];" \
        : "=r"((r)[0]), "=r"((r)[1]), "=r"((r)[2]), "=r"((r)[3]) : "r"(p))
#define LDSM_X4T(r, p) \
    asm volatile("ldmatrix.sync.aligned.m8n8.x4.trans.shared.b16 {%0,%1,%2,%3}, [%4];" \
        : "=r"((r)[0]), "=r"((r)[1]), "=r"((r)[2]), "=r"((r)[3]) : "r"(p))

// ---------------------------------------------------------------------------
__global__ __launch_bounds__(256) void prep_x(const float* __restrict__ stim,
                                              const float* __restrict__ prev)
{
    int mat = blockIdx.y;
    const float* X = mat ? prev : stim;
    int idx = blockIdx.x * 256 + threadIdx.x;
    float x = X[idx];
    __nv_bfloat16 hi = __float2bfloat16(x);
    __nv_bfloat16 lo = __float2bfloat16(x - __bfloat162float(hi));
    int b = idx >> 12, d = idx & 4095;
    g_xsp[mat][b][d] = hi;
    g_xsp[mat][b + 32][d] = lo;
}

// ---------------------------------------------------------------------------
// fwd via mma.sync bf16 hi/lo, coalesced W staging + ldmatrix.trans.
// CTA: (n-tile 64, split of K=1024, mat). 128 threads = 4 warps x n16.
// M=64 ([hi(X);lo(X)]); partial -> g_fpart[split][mat].
// ---------------------------------------------------------------------------
__global__ __launch_bounds__(128) void fwd_mma2(
    const float* __restrict__ Wh, const float* __restrict__ Wr)
{
    const int mat = blockIdx.z;
    const float* __restrict__ W = mat ? Wr : Wh;
    const int n0 = blockIdx.x * 64;
    const int kbase = blockIdx.y * 1024;

    __shared__ __nv_bfloat16 As[64][72];
    __shared__ __nv_bfloat16 Bh[64][72];
    __shared__ __nv_bfloat16 Bl[64][72];

    const int tid = threadIdx.x;
    const int lane = tid & 31;
    const int wid = tid >> 5;
    const int nloc = wid << 4;

    // A ldmatrix lane addressing (non-trans x4)
    const int lsub = lane >> 3;
    const int arow = (lane & 7) + ((lsub & 1) << 3);
    const int acol = (lsub & 2) << 2;
    // B ldmatrix lane addressing (trans x4): row-major [k][n] tile
    const int brow = (lane & 7) + ((lane & 8) ? 8 : 0);
    const int bcol = nloc + ((lane & 16) ? 8 : 0);

    float d[4][2][4] = {};
    uint4 areg[4];
    float4 wreg[8];

    // prefetch chunk 0
    {
        const int k0 = kbase;
        #pragma unroll
        for (int r = 0; r < 4; ++r) {
            int idx = tid + r * 128;
            areg[r] = *(const uint4*)&g_xsp[mat][idx >> 3][k0 + (idx & 7) * 8];
        }
        #pragma unroll
        for (int r = 0; r < 8; ++r) {
            int idx = tid + r * 128;
            wreg[r] = *(const float4*)&W[(size_t)(k0 + (idx >> 4)) * Dn + n0 + (idx & 15) * 4];
        }
    }

    for (int c = 0; c < 16; ++c) {
        // stage regs -> smem (A copy, W convert to bf16 hi/lo)
        #pragma unroll
        for (int r = 0; r < 4; ++r) {
            int idx = tid + r * 128;
            *(uint4*)&As[idx >> 3][(idx & 7) * 8] = areg[r];
        }
        #pragma unroll
        for (int r = 0; r < 8; ++r) {
            int idx = tid + r * 128;
            int row = idx >> 4, col = (idx & 15) * 4;
            float4 w = wreg[r];
            uint32_t h0 = pack_hi(w.x, w.y), h1 = pack_hi(w.z, w.w);
            uint32_t l0 = pack_lo(w.x, w.y), l1 = pack_lo(w.z, w.w);
            asm volatile("st.shared.v2.b32 [%0], {%1,%2};"
                :: "r"(smem_u32(&Bh[row][col])), "r"(h0), "r"(h1) : "memory");
            asm volatile("st.shared.v2.b32 [%0], {%1,%2};"
                :: "r"(smem_u32(&Bl[row][col])), "r"(l0), "r"(l1) : "memory");
        }
        __syncthreads();
        if (c < 15) {
            const int k0 = kbase + (c + 1) * 64;
            #pragma unroll
            for (int r = 0; r < 4; ++r) {
                int idx = tid + r * 128;
                areg[r] = *(const uint4*)&g_xsp[mat][idx >> 3][k0 + (idx & 7) * 8];
            }
            #pragma unroll
            for (int r = 0; r < 8; ++r) {
                int idx = tid + r * 128;
                wreg[r] = *(const float4*)&W[(size_t)(k0 + (idx >> 4)) * Dn + n0 + (idx & 15) * 4];
            }
        }
        #pragma unroll
        for (int kk = 0; kk < 4; ++kk) {
            uint32_t bh[4], bl[4];
            LDSM_X4T(bh, smem_u32(&Bh[kk * 16 + brow][bcol]));
            LDSM_X4T(bl, smem_u32(&Bl[kk * 16 + brow][bcol]));
            #pragma unroll
            for (int mt = 0; mt < 4; ++mt) {
                uint32_t a[4];
                LDSM_X4(a, smem_u32(&As[mt * 16 + arow][kk * 16 + acol]));
                mma16816(d[mt][0], a, bh[0], bh[1]);
                mma16816(d[mt][1], a, bh[2], bh[3]);
                mma16816(d[mt][0], a, bl[0], bl[1]);
                mma16816(d[mt][1], a, bl[2], bl[3]);
            }
        }
        __syncthreads();
    }

    // epilogue: hi rows (mt 0,1) + lo rows (mt 2,3) -> partial
    float* P = &g_fpart[blockIdx.y][mat][0][0];
    const int g = lane >> 2, cc = (lane & 3) * 2;
    #pragma unroll
    for (int h = 0; h < 2; ++h) {
        #pragma unroll
        for (int j = 0; j < 2; ++j) {
            float v0 = d[h][j][0] + d[h + 2][j][0];
            float v1 = d[h][j][1] + d[h + 2][j][1];
            float v2 = d[h][j][2] + d[h + 2][j][2];
            float v3 = d[h][j][3] + d[h + 2][j][3];
            int r0 = h * 16 + g;
            int col = n0 + nloc + j * 8 + cc;
            *(float2*)&P[r0 * Dn + col] = make_float2(v0, v1);
            *(float2*)&P[(r0 + 8) * Dn + col] = make_float2(v2, v3);
        }
    }
}

// ---------------------------------------------------------------------------
__global__ __launch_bounds__(256) void reduce_relu_kernel()
{
    int f = blockIdx.x * 256 + threadIdx.x;   // float4 index, 65536 total
    const float4* p = (const float4*)&g_fpart[0][0][0][0];
    float4 a = p[f];
    #pragma unroll
    for (int s = 1; s < 4; ++s) {
        float4 b = p[s * 65536 + f];
        a.x += b.x; a.y += b.y; a.z += b.z; a.w += b.w;
    }
    a.x = fmaxf(a.x, 0.f); a.y = fmaxf(a.y, 0.f);
    a.z = fmaxf(a.z, 0.f); a.w = fmaxf(a.w, 0.f);
    ((float4*)&g_act[0][0])[f] = a;
}

// ---------------------------------------------------------------------------
__global__ __launch_bounds__(256) void ln_final_kernel(
    const float* __restrict__ gamma, const float* __restrict__ beta,
    float* __restrict__ out)
{
    const int row = blockIdx.x;
    const float* rec = g_act[1] + row * Dn;
    const float* stm = g_act[0] + row * Dn;
    float s = 0.f, ss = 0.f;
    for (int i = threadIdx.x; i < Dn; i += 256) {
        float v = rec[i]; s += v; ss += v * v;
    }
    __shared__ float rs[256], rq[256];
    rs[threadIdx.x] = s; rq[threadIdx.x] = ss;
    __syncthreads();
    for (int off = 128; off > 0; off >>= 1) {
        if (threadIdx.x < off) {
            rs[threadIdx.x] += rs[threadIdx.x + off];
            rq[threadIdx.x] += rq[threadIdx.x + off];
        }
        __syncthreads();
    }
    float mean = rs[0] * (1.f / Dn);
    float var  = rq[0] * (1.f / Dn) - mean * mean;
    float inv  = rsqrtf(var + 1e-5f);
    for (int i = threadIdx.x; i < Dn; i += 256)
        out[row * Dn + i] = (rec[i] - mean) * inv * gamma[i] + beta[i] + stm[i];
}

// ---------------------------------------------------------------------------
__global__ __launch_bounds__(256) void mlp_gemm2(
    const float* __restrict__ xext, int insel,
    const float* __restrict__ W, int K, int N, int Kc, int psel)
{
    const float* __restrict__ X = (insel == 0) ? xext : g_h1;
    float* __restrict__ P = (psel == 1) ? &g_mp1[0][0][0] : &g_mp2[0][0][0];
    const int n0 = blockIdx.x * 128;
    const int kbase = blockIdx.y * Kc;
    const int iters = Kc >> 5;

    __shared__ float Xs[32][36];
    __shared__ float Ws[32][128];
    const int tid = threadIdx.x;
    const int xrow = tid >> 3, xk = (tid & 7) << 2;
    const int wk = tid >> 5, wn = (tid & 31) << 2;
    const int tx = tid & 31, ty = tid >> 5;

    float4 xr  = *(const float4*)&X[xrow * K + kbase + xk];
    float4 wr0 = *(const float4*)&W[(size_t)(kbase + wk +  0) * N + n0 + wn];
    float4 wr1 = *(const float4*)&W[(size_t)(kbase + wk +  8) * N + n0 + wn];
    float4 wr2 = *(const float4*)&W[(size_t)(kbase + wk + 16) * N + n0 + wn];
    float4 wr3 = *(const float4*)&W[(size_t)(kbase + wk + 24) * N + n0 + wn];
    float acc[4][4] = {};

    for (int c = 0; c < iters; ++c) {
        Xs[xk + 0][xrow] = xr.x; Xs[xk + 1][xrow] = xr.y;
        Xs[xk + 2][xrow] = xr.z; Xs[xk + 3][xrow] = xr.w;
        *(float4*)&Ws[wk +  0][wn] = wr0;
        *(float4*)&Ws[wk +  8][wn] = wr1;
        *(float4*)&Ws[wk + 16][wn] = wr2;
        *(float4*)&Ws[wk + 24][wn] = wr3;
        __syncthreads();
        if (c + 1 < iters) {
            int k = kbase + (c + 1) * 32;
            xr  = *(const float4*)&X[xrow * K + k + xk];
            wr0 = *(const float4*)&W[(size_t)(k + wk +  0) * N + n0 + wn];
            wr1 = *(const float4*)&W[(size_t)(k + wk +  8) * N + n0 + wn];
            wr2 = *(const float4*)&W[(size_t)(k + wk + 16) * N + n0 + wn];
            wr3 = *(const float4*)&W[(size_t)(k + wk + 24) * N + n0 + wn];
        }
        #pragma unroll 8
        for (int kk = 0; kk < 32; ++kk) {
            float4 a = *(const float4*)&Xs[kk][ty << 2];
            float4 b = *(const float4*)&Ws[kk][tx << 2];
            acc[0][0] = fmaf(a.x, b.x, acc[0][0]); acc[0][1] = fmaf(a.x, b.y, acc[0][1]);
            acc[0][2] = fmaf(a.x, b.z, acc[0][2]); acc[0][3] = fmaf(a.x, b.w, acc[0][3]);
            acc[1][0] = fmaf(a.y, b.x, acc[1][0]); acc[1][1] = fmaf(a.y, b.y, acc[1][1]);
            acc[1][2] = fmaf(a.y, b.z, acc[1][2]); acc[1][3] = fmaf(a.y, b.w, acc[1][3]);
            acc[2][0] = fmaf(a.z, b.x, acc[2][0]); acc[2][1] = fmaf(a.z, b.y, acc[2][1]);
            acc[2][2] = fmaf(a.z, b.z, acc[2][2]); acc[2][3] = fmaf(a.z, b.w, acc[2][3]);
            acc[3][0] = fmaf(a.w, b.x, acc[3][0]); acc[3][1] = fmaf(a.w, b.y, acc[3][1]);
            acc[3][2] = fmaf(a.w, b.z, acc[3][2]); acc[3][3] = fmaf(a.w, b.w, acc[3][3]);
        }
        __syncthreads();
    }
    #pragma unroll
    for (int m = 0; m < 4; ++m) {
        int row = (ty << 2) + m;
        float4 v = make_float4(acc[m][0], acc[m][1], acc[m][2], acc[m][3]);
        *(float4*)&P[((size_t)blockIdx.y * Bn + row) * N + n0 + (tx << 2)] = v;
    }
}

// ---------------------------------------------------------------------------
__global__ __launch_bounds__(256) void fc3_gemm(const float* __restrict__ W)
{
    const int kb = blockIdx.x * 32;
    __shared__ float Xs[32][33];
    __shared__ float Ws[32][64];
    const int tid = threadIdx.x;
    const int xrow = tid >> 3, xk = (tid & 7) << 2;
    const int kw = tid >> 4, wn = (tid & 15) << 2;

    float4 xv = *(const float4*)&g_h2[xrow * 256 + kb + xk];
    Xs[xk + 0][xrow] = xv.x; Xs[xk + 1][xrow] = xv.y;
    Xs[xk + 2][xrow] = xv.z; Xs[xk + 3][xrow] = xv.w;
    *(float4*)&Ws[kw +  0][wn] = *(const float4*)&W[(kb + kw +  0) * 64 + wn];
    *(float4*)&Ws[kw + 16][wn] = *(const float4*)&W[(kb + kw + 16) * 64 + wn];
    __syncthreads();

    const int tx = tid & 15, ty = tid >> 4;
    float acc[2][4] = {};
    #pragma unroll 8
    for (int kk = 0; kk < 32; ++kk) {
        float a0 = Xs[kk][ty * 2 + 0], a1 = Xs[kk][ty * 2 + 1];
        float4 b = *(const float4*)&Ws[kk][tx << 2];
        acc[0][0] = fmaf(a0, b.x, acc[0][0]); acc[0][1] = fmaf(a0, b.y, acc[0][1]);
        acc[0][2] = fmaf(a0, b.z, acc[0][2]); acc[0][3] = fmaf(a0, b.w, acc[0][3]);
        acc[1][0] = fmaf(a1, b.x, acc[1][0]); acc[1][1] = fmaf(a1, b.y, acc[1][1]);
        acc[1][2] = fmaf(a1, b.z, acc[1][2]); acc[1][3] = fmaf(a1, b.w, acc[1][3]);
    }
    #pragma unroll
    for (int m = 0; m < 2; ++m) {
        int row = ty * 2 + m;
        float4 v = make_float4(acc[m][0], acc[m][1], acc[m][2], acc[m][3]);
        *(float4*)&g_mp3[blockIdx.x][row][tx << 2] = v;
    }
}

// ---------------------------------------------------------------------------
__global__ __launch_bounds__(256) void lnact_reduce(
    int psel, int S, int N, const float* __restrict__ bias,
    const float* __restrict__ gamma, const float* __restrict__ beta, int act)
{
    const float* part = (psel == 1) ? &g_mp1[0][0][0]
                      : (psel == 2) ? &g_mp2[0][0][0] : &g_mp3[0][0][0];
    float* outb = (psel == 1) ? g_h1 : (psel == 2) ? g_h2 : g_o;
    const int row = blockIdx.x;
    __shared__ float vbuf[512];
    float s = 0.f, ss = 0.f;
    for (int i = threadIdx.x; i < N; i += 256) {
        float v = bias[i];
        for (int sp = 0; sp < S; ++sp)
            v += part[((size_t)sp * Bn + row) * N + i];
        vbuf[i] = v; s += v; ss += v * v;
    }
    __shared__ float rs[256], rq[256];
    rs[threadIdx.x] = s; rq[threadIdx.x] = ss;
    __syncthreads();
    for (int off = 128; off > 0; off >>= 1) {
        if (threadIdx.x < off) {
            rs[threadIdx.x] += rs[threadIdx.x + off];
            rq[threadIdx.x] += rq[threadIdx.x + off];
        }
        __syncthreads();
    }
    float mean = rs[0] / (float)N;
    float var  = rq[0] / (float)N - mean * mean;
    float inv  = rsqrtf(var + 1e-5f);
    for (int i = threadIdx.x; i < N; i += 256) {
        float v = (vbuf[i] - mean) * inv * gamma[i] + beta[i];
        outb[row * N + i] = (act == 1) ? fmaxf(v, 0.f) : tanhf(v);
    }
}

// ---------------------------------------------------------------------------
__global__ __launch_bounds__(256) void alpha_kernel()
{
    __shared__ float dsh[Un];
    int t = threadIdx.x;
    if (t < Un) {
        float s = 0.f;
        #pragma unroll
        for (int b = 0; b < Bn; b++) s += g_o[b * Un + t];
        dsh[t] = s * (9.9f / (float)Bn);
    }
    __syncthreads();
    for (int d = t; d < Dn; d += 256) g_alpha[d] = dsh[d >> 6];
}

// ---------------------------------------------------------------------------
__global__ __launch_bounds__(256) void update_kernel(
    const float* __restrict__ stim, const float* __restrict__ prev,
    const float* __restrict__ Wh, const float* __restrict__ Wr,
    const float* __restrict__ decay, float* __restrict__ out)
{
    const int mat = blockIdx.z;
    const float* __restrict__ A = mat ? prev : stim;
    const float* __restrict__ C = g_act[mat];
    const float* __restrict__ W = mat ? Wr : Wh;
    float* __restrict__ O = out + (size_t)(Bn + mat * Dn) * Dn;
    const int i0 = blockIdx.y * 64;
    const int j0 = blockIdx.x * 64;

    __shared__ float As[32][64];
    __shared__ float Cs[32][64];
    __shared__ float red[64][17];

    const int tid = threadIdx.x;
    for (int idx = tid; idx < 32 * 64; idx += 256) {
        int b = idx >> 6, c = idx & 63;
        As[b][c] = A[b * Dn + i0 + c];
        Cs[b][c] = C[b * Dn + j0 + c];
    }
    __syncthreads();

    const int tx = tid & 15, ty = tid >> 4;
    unsigned long long acc2[4][2] = {};
    #pragma unroll
    for (int b = 0; b < 32; b++) {
        float4 a4 = *(const float4*)&As[b][ty * 4];
        ulonglong2 c2 = *(const ulonglong2*)&Cs[b][tx * 4];
        unsigned long long am;
        PACK2(am, a4.x, a4.x); FMA2(acc2[0][0], am, c2.x); FMA2(acc2[0][1], am, c2.y);
        PACK2(am, a4.y, a4.y); FMA2(acc2[1][0], am, c2.x); FMA2(acc2[1][1], am, c2.y);
        PACK2(am, a4.z, a4.z); FMA2(acc2[2][0], am, c2.x); FMA2(acc2[2][1], am, c2.y);
        PACK2(am, a4.w, a4.w); FMA2(acc2[3][0], am, c2.x); FMA2(acc2[3][1], am, c2.y);
    }

    float4 al = *(const float4*)&g_alpha[j0 + tx * 4];
    float alv[4] = {al.x, al.y, al.z, al.w};
    #pragma unroll
    for (int m = 0; m < 4; m++) {
        int i = i0 + ty * 4 + m;
        float dm = 1.0f - decay[i];
        float4 w4 = *(const float4*)&W[(size_t)i * Dn + j0 + tx * 4];
        float wv[4] = {w4.x, w4.y, w4.z, w4.w};
        float ac[4];
        UNPK2(ac[0], ac[1], acc2[m][0]);
        UNPK2(ac[2], ac[3], acc2[m][1]);
        float v[4], ssum = 0.f;
        #pragma unroll
        for (int n = 0; n < 4; n++) {
            v[n] = (wv[n] + ac[n] * alv[n]) * dm;
            ssum = fmaf(v[n], v[n], ssum);
        }
        float4 o4 = {v[0], v[1], v[2], v[3]};
        *(float4*)&O[(size_t)i * Dn + j0 + tx * 4] = o4;
        red[ty * 4 + m][tx] = ssum;
    }
    __syncthreads();
    if (tid < 64) {
        float s = 0.f;
        #pragma unroll
        for (int t = 0; t < 16; t++) s += red[tid][t];
        g_part[mat][blockIdx.x][i0 + tid] = s;
    }
}

// ---------------------------------------------------------------------------
__global__ __launch_bounds__(256) void norm_reduce_kernel()
{
    int mat = blockIdx.y;
    int i = blockIdx.x * 256 + threadIdx.x;
    float s = 0.f;
    #pragma unroll 8
    for (int jb = 0; jb < 64; jb++) s += g_part[mat][jb][i];
    g_norm[mat][i] = s;
}

// ---------------------------------------------------------------------------
__global__ __launch_bounds__(256) void scale_kernel(float* __restrict__ out)
{
    float4* base = (float4*)(out + (size_t)Bn * Dn);
    int t0 = blockIdx.x * 1024 + threadIdx.x;
    #pragma unroll
    for (int r = 0; r < 4; r++) {
        int idx = t0 + r * 256;
        size_t e = (size_t)idx << 2;
        int mat = (int)(e >> 24);
        int i = (int)((e >> 12) & (Dn - 1));
        float sc = 1.0f / fmaxf(sqrtf(g_norm[mat][i]), 1e-12f);
        float4 v = base[idx];
        v.x *= sc; v.y *= sc; v.z *= sc; v.w *= sc;
        base[idx] = v;
    }
}

// ---------------------------------------------------------------------------
extern "C" void kernel_launch(void* const* d_in, const int* in_sizes, int n_in,
                              void* d_out, int out_size)
{
    const float* stimulus = (const float*)d_in[0];
    const float* prev_act = (const float*)d_in[1];
    const float* W_heb    = (const float*)d_in[2];
    const float* W_rec    = (const float*)d_in[3];
    const float* decay    = (const float*)d_in[4];
    const float* ln_rec_g = (const float*)d_in[5];
    const float* ln_rec_b = (const float*)d_in[6];
    const float* fc1_w    = (const float*)d_in[7];
    const float* fc1_b    = (const float*)d_in[8];
    const float* ln1_g    = (const float*)d_in[9];
    const float* ln1_b    = (const float*)d_in[10];
    const float* fc2_w    = (const float*)d_in[11];
    const float* fc2_b    = (const float*)d_in[12];
    const float* ln2_g    = (const float*)d_in[13];
    const float* ln2_b    = (const float*)d_in[14];
    const float* fc3_w    = (const float*)d_in[15];
    const float* fc3_b    = (const float*)d_in[16];
    const float* lno_g    = (const float*)d_in[17];
    const float* lno_b    = (const float*)d_in[18];
    float* out = (float*)d_out;

    prep_x<<<dim3(512, 2), 256>>>(stimulus, prev_act);
    fwd_mma2<<<dim3(64, 4, 2), 128>>>(W_heb, W_rec);
    reduce_relu_kernel<<<256, 256>>>();
    ln_final_kernel<<<32, 256>>>(ln_rec_g, ln_rec_b, out);
    mlp_gemm2<<<dim3(4, 32), 256>>>(out, 0, fc1_w, 4096, 512, 128, 1);
    lnact_reduce<<<32, 256>>>(1, 32, 512, fc1_b, ln1_g, ln1_b, 1);
    mlp_gemm2<<<dim3(2, 8), 256>>>(nullptr, 1, fc2_w, 512, 256, 64, 2);
    lnact_reduce<<<32, 256>>>(2, 8, 256, fc2_b, ln2_g, ln2_b, 1);
    fc3_gemm<<<8, 256>>>(fc3_w);
    lnact_reduce<<<32, 256>>>(3, 8, 64, fc3_b, lno_g, lno_b, 2);
    alpha_kernel<<<1, 256>>>();
    update_kernel<<<dim3(64, 64, 2), 256>>>(stimulus, prev_act, W_heb, W_rec, decay, out);
    norm_reduce_kernel<<<dim3(16, 2), 256>>>();
    scale_kernel<<<8192, 256>>>(out);
}

// round 7
// speedup vs baseline: 1.6423x; 1.0224x over previous
#include <cuda_runtime.h>
#include <cuda_bf16.h>
#include <math.h>
#include <stdint.h>

#define Dn 4096
#define Bn 32
#define Un 64

__device__ __nv_bfloat16 g_xsp[2][64][Dn];  // rows 0-31 hi(X), 32-63 lo(X)
__device__ float g_fpart[4][2][Bn][Dn];     // fwd split-K partials
__device__ float g_act[2][Bn * Dn];
__device__ float g_mp1[32][Bn][512];
__device__ float g_h1[Bn * 512];
__device__ float g_o[Bn * Un];
__device__ float g_alpha[Dn];
__device__ float g_norm[2][Dn];
__device__ float g_part[2][32][Dn];

#define PACK2(v, lo, hi) asm("mov.b64 %0, {%1, %2};" : "=l"(v) : "f"(lo), "f"(hi))
#define UNPK2(lo, hi, v) asm("mov.b64 {%0, %1}, %2;" : "=f"(lo), "=f"(hi) : "l"(v))
#define FMA2(d, a, b) asm("fma.rn.f32x2 %0, %1, %2, %0;" : "+l"(d) : "l"(a), "l"(b))

__device__ __forceinline__ uint32_t smem_u32(const void* p) {
    uint32_t a;
    asm("{ .reg .u64 t; cvta.to.shared.u64 t, %1; cvt.u32.u64 %0, t; }" : "=r"(a) : "l"(p));
    return a;
}
__device__ __forceinline__ uint32_t pack_hi(float f0, float f1) {
    return (uint32_t)__bfloat16_as_ushort(__float2bfloat16(f0))
         | ((uint32_t)__bfloat16_as_ushort(__float2bfloat16(f1)) << 16);
}
__device__ __forceinline__ uint32_t pack_lo(float f0, float f1) {
    float r0 = f0 - __bfloat162float(__float2bfloat16(f0));
    float r1 = f1 - __bfloat162float(__float2bfloat16(f1));
    return pack_hi(r0, r1);
}
__device__ __forceinline__ void mma16816(float* d, const uint32_t* a,
                                         uint32_t b0, uint32_t b1) {
    asm volatile(
        "mma.sync.aligned.m16n8k16.row.col.f32.bf16.bf16.f32 "
        "{%0,%1,%2,%3}, {%4,%5,%6,%7}, {%8,%9}, {%0,%1,%2,%3};"
        : "+f"(d[0]), "+f"(d[1]), "+f"(d[2]), "+f"(d[3])
        : "r"(a[0]), "r"(a[1]), "r"(a[2]), "r"(a[3]), "r"(b0), "r"(b1));
}
#define LDSM_X4(r, p) \
    asm volatile("ldmatrix.sync.aligned.m8n8.x4.shared.b16 {%0,%1,%2,%3}, [%4];" \
        : "=r"((r)[0]), "=r"((r)[1]), "=r"((r)[2]), "=r"((r)[3]) : "r"(p))
#define LDSM_X4T(r, p) \
    asm volatile("ldmatrix.sync.aligned.m8n8.x4.trans.shared.b16 {%0,%1,%2,%3}, [%4];" \
        : "=r"((r)[0]), "=r"((r)[1]), "=r"((r)[2]), "=r"((r)[3]) : "r"(p))

// ---------------------------------------------------------------------------
__global__ __launch_bounds__(256) void prep_x(const float* __restrict__ stim,
                                              const float* __restrict__ prev)
{
    int mat = blockIdx.y;
    const float* X = mat ? prev : stim;
    int idx = blockIdx.x * 256 + threadIdx.x;
    float x = X[idx];
    __nv_bfloat16 hi = __float2bfloat16(x);
    __nv_bfloat16 lo = __float2bfloat16(x - __bfloat162float(hi));
    int b = idx >> 12, d = idx & 4095;
    g_xsp[mat][b][d] = hi;
    g_xsp[mat][b + 32][d] = lo;
}

// ---------------------------------------------------------------------------
// fwd via mma.sync bf16 hi/lo, coalesced W staging + ldmatrix.trans.
// ---------------------------------------------------------------------------
__global__ __launch_bounds__(128) void fwd_mma2(
    const float* __restrict__ Wh, const float* __restrict__ Wr)
{
    const int mat = blockIdx.z;
    const float* __restrict__ W = mat ? Wr : Wh;
    const int n0 = blockIdx.x * 64;
    const int kbase = blockIdx.y * 1024;

    __shared__ __nv_bfloat16 As[64][72];
    __shared__ __nv_bfloat16 Bh[64][72];
    __shared__ __nv_bfloat16 Bl[64][72];

    const int tid = threadIdx.x;
    const int lane = tid & 31;
    const int wid = tid >> 5;
    const int nloc = wid << 4;

    const int lsub = lane >> 3;
    const int arow = (lane & 7) + ((lsub & 1) << 3);
    const int acol = (lsub & 2) << 2;
    const int brow = (lane & 7) + ((lane & 8) ? 8 : 0);
    const int bcol = nloc + ((lane & 16) ? 8 : 0);

    float d[4][2][4] = {};
    uint4 areg[4];
    float4 wreg[8];

    {
        const int k0 = kbase;
        #pragma unroll
        for (int r = 0; r < 4; ++r) {
            int idx = tid + r * 128;
            areg[r] = *(const uint4*)&g_xsp[mat][idx >> 3][k0 + (idx & 7) * 8];
        }
        #pragma unroll
        for (int r = 0; r < 8; ++r) {
            int idx = tid + r * 128;
            wreg[r] = *(const float4*)&W[(size_t)(k0 + (idx >> 4)) * Dn + n0 + (idx & 15) * 4];
        }
    }

    for (int c = 0; c < 16; ++c) {
        #pragma unroll
        for (int r = 0; r < 4; ++r) {
            int idx = tid + r * 128;
            *(uint4*)&As[idx >> 3][(idx & 7) * 8] = areg[r];
        }
        #pragma unroll
        for (int r = 0; r < 8; ++r) {
            int idx = tid + r * 128;
            int row = idx >> 4, col = (idx & 15) * 4;
            float4 w = wreg[r];
            uint32_t h0 = pack_hi(w.x, w.y), h1 = pack_hi(w.z, w.w);
            uint32_t l0 = pack_lo(w.x, w.y), l1 = pack_lo(w.z, w.w);
            asm volatile("st.shared.v2.b32 [%0], {%1,%2};"
                :: "r"(smem_u32(&Bh[row][col])), "r"(h0), "r"(h1) : "memory");
            asm volatile("st.shared.v2.b32 [%0], {%1,%2};"
                :: "r"(smem_u32(&Bl[row][col])), "r"(l0), "r"(l1) : "memory");
        }
        __syncthreads();
        if (c < 15) {
            const int k0 = kbase + (c + 1) * 64;
            #pragma unroll
            for (int r = 0; r < 4; ++r) {
                int idx = tid + r * 128;
                areg[r] = *(const uint4*)&g_xsp[mat][idx >> 3][k0 + (idx & 7) * 8];
            }
            #pragma unroll
            for (int r = 0; r < 8; ++r) {
                int idx = tid + r * 128;
                wreg[r] = *(const float4*)&W[(size_t)(k0 + (idx >> 4)) * Dn + n0 + (idx & 15) * 4];
            }
        }
        #pragma unroll
        for (int kk = 0; kk < 4; ++kk) {
            uint32_t bh[4], bl[4];
            LDSM_X4T(bh, smem_u32(&Bh[kk * 16 + brow][bcol]));
            LDSM_X4T(bl, smem_u32(&Bl[kk * 16 + brow][bcol]));
            #pragma unroll
            for (int mt = 0; mt < 4; ++mt) {
                uint32_t a[4];
                LDSM_X4(a, smem_u32(&As[mt * 16 + arow][kk * 16 + acol]));
                mma16816(d[mt][0], a, bh[0], bh[1]);
                mma16816(d[mt][1], a, bh[2], bh[3]);
                mma16816(d[mt][0], a, bl[0], bl[1]);
                mma16816(d[mt][1], a, bl[2], bl[3]);
            }
        }
        __syncthreads();
    }

    float* P = &g_fpart[blockIdx.y][mat][0][0];
    const int g = lane >> 2, cc = (lane & 3) * 2;
    #pragma unroll
    for (int h = 0; h < 2; ++h) {
        #pragma unroll
        for (int j = 0; j < 2; ++j) {
            float v0 = d[h][j][0] + d[h + 2][j][0];
            float v1 = d[h][j][1] + d[h + 2][j][1];
            float v2 = d[h][j][2] + d[h + 2][j][2];
            float v3 = d[h][j][3] + d[h + 2][j][3];
            int r0 = h * 16 + g;
            int col = n0 + nloc + j * 8 + cc;
            *(float2*)&P[r0 * Dn + col] = make_float2(v0, v1);
            *(float2*)&P[(r0 + 8) * Dn + col] = make_float2(v2, v3);
        }
    }
}

// ---------------------------------------------------------------------------
// Fused: split-reduce + relu (both mats) -> g_act ; LN(rec)+stim -> out row.
// grid 32 (one per batch row), 1024 threads, 1 float4/thread/row.
// ---------------------------------------------------------------------------
__global__ __launch_bounds__(1024) void lnfinal_fused(
    const float* __restrict__ gamma, const float* __restrict__ beta,
    float* __restrict__ out)
{
    const int row = blockIdx.x;
    const int t = threadIdx.x;
    const int lane = t & 31, wid = t >> 5;
    const float4* fp = (const float4*)&g_fpart[0][0][0][0];

    // stim = relu(sum splits, mat 0)
    float4 a = fp[(size_t)((0 * 2 + 0) * 32 + row) * 1024 + t];
    #pragma unroll
    for (int s = 1; s < 4; ++s) {
        float4 b = fp[(size_t)((s * 2 + 0) * 32 + row) * 1024 + t];
        a.x += b.x; a.y += b.y; a.z += b.z; a.w += b.w;
    }
    float4 stim = make_float4(fmaxf(a.x, 0.f), fmaxf(a.y, 0.f),
                              fmaxf(a.z, 0.f), fmaxf(a.w, 0.f));
    ((float4*)&g_act[0][row * Dn])[t] = stim;

    // rec = relu(sum splits, mat 1)
    a = fp[(size_t)((0 * 2 + 1) * 32 + row) * 1024 + t];
    #pragma unroll
    for (int s = 1; s < 4; ++s) {
        float4 b = fp[(size_t)((s * 2 + 1) * 32 + row) * 1024 + t];
        a.x += b.x; a.y += b.y; a.z += b.z; a.w += b.w;
    }
    float4 rec = make_float4(fmaxf(a.x, 0.f), fmaxf(a.y, 0.f),
                             fmaxf(a.z, 0.f), fmaxf(a.w, 0.f));
    ((float4*)&g_act[1][row * Dn])[t] = rec;

    // LN reduce over 4096
    float s = rec.x + rec.y + rec.z + rec.w;
    float q = rec.x * rec.x + rec.y * rec.y + rec.z * rec.z + rec.w * rec.w;
    #pragma unroll
    for (int off = 16; off > 0; off >>= 1) {
        s += __shfl_down_sync(0xFFFFFFFF, s, off);
        q += __shfl_down_sync(0xFFFFFFFF, q, off);
    }
    __shared__ float rs[32], rq[32], stats[2];
    if (lane == 0) { rs[wid] = s; rq[wid] = q; }
    __syncthreads();
    if (wid == 0) {
        s = rs[lane]; q = rq[lane];
        #pragma unroll
        for (int off = 16; off > 0; off >>= 1) {
            s += __shfl_down_sync(0xFFFFFFFF, s, off);
            q += __shfl_down_sync(0xFFFFFFFF, q, off);
        }
        if (lane == 0) {
            float mean = s * (1.f / Dn);
            float var = q * (1.f / Dn) - mean * mean;
            stats[0] = mean;
            stats[1] = rsqrtf(var + 1e-5f);
        }
    }
    __syncthreads();
    float mean = stats[0], inv = stats[1];
    float4 gm = ((const float4*)gamma)[t];
    float4 bt = ((const float4*)beta)[t];
    float4 o;
    o.x = (rec.x - mean) * inv * gm.x + bt.x + stim.x;
    o.y = (rec.y - mean) * inv * gm.y + bt.y + stim.y;
    o.z = (rec.z - mean) * inv * gm.z + bt.z + stim.z;
    o.w = (rec.w - mean) * inv * gm.w + bt.w + stim.w;
    ((float4*)&out[row * Dn])[t] = o;
}

// ---------------------------------------------------------------------------
// fc1 split-K GEMM (unchanged path)
// ---------------------------------------------------------------------------
__global__ __launch_bounds__(256) void mlp_gemm2(
    const float* __restrict__ X, const float* __restrict__ W, int K, int N, int Kc)
{
    float* __restrict__ P = &g_mp1[0][0][0];
    const int n0 = blockIdx.x * 128;
    const int kbase = blockIdx.y * Kc;
    const int iters = Kc >> 5;

    __shared__ float Xs[32][36];
    __shared__ float Ws[32][128];
    const int tid = threadIdx.x;
    const int xrow = tid >> 3, xk = (tid & 7) << 2;
    const int wk = tid >> 5, wn = (tid & 31) << 2;
    const int tx = tid & 31, ty = tid >> 5;

    float4 xr  = *(const float4*)&X[xrow * K + kbase + xk];
    float4 wr0 = *(const float4*)&W[(size_t)(kbase + wk +  0) * N + n0 + wn];
    float4 wr1 = *(const float4*)&W[(size_t)(kbase + wk +  8) * N + n0 + wn];
    float4 wr2 = *(const float4*)&W[(size_t)(kbase + wk + 16) * N + n0 + wn];
    float4 wr3 = *(const float4*)&W[(size_t)(kbase + wk + 24) * N + n0 + wn];
    float acc[4][4] = {};

    for (int c = 0; c < iters; ++c) {
        Xs[xk + 0][xrow] = xr.x; Xs[xk + 1][xrow] = xr.y;
        Xs[xk + 2][xrow] = xr.z; Xs[xk + 3][xrow] = xr.w;
        *(float4*)&Ws[wk +  0][wn] = wr0;
        *(float4*)&Ws[wk +  8][wn] = wr1;
        *(float4*)&Ws[wk + 16][wn] = wr2;
        *(float4*)&Ws[wk + 24][wn] = wr3;
        __syncthreads();
        if (c + 1 < iters) {
            int k = kbase + (c + 1) * 32;
            xr  = *(const float4*)&X[xrow * K + k + xk];
            wr0 = *(const float4*)&W[(size_t)(k + wk +  0) * N + n0 + wn];
            wr1 = *(const float4*)&W[(size_t)(k + wk +  8) * N + n0 + wn];
            wr2 = *(const float4*)&W[(size_t)(k + wk + 16) * N + n0 + wn];
            wr3 = *(const float4*)&W[(size_t)(k + wk + 24) * N + n0 + wn];
        }
        #pragma unroll 8
        for (int kk = 0; kk < 32; ++kk) {
            float4 a = *(const float4*)&Xs[kk][ty << 2];
            float4 b = *(const float4*)&Ws[kk][tx << 2];
            acc[0][0] = fmaf(a.x, b.x, acc[0][0]); acc[0][1] = fmaf(a.x, b.y, acc[0][1]);
            acc[0][2] = fmaf(a.x, b.z, acc[0][2]); acc[0][3] = fmaf(a.x, b.w, acc[0][3]);
            acc[1][0] = fmaf(a.y, b.x, acc[1][0]); acc[1][1] = fmaf(a.y, b.y, acc[1][1]);
            acc[1][2] = fmaf(a.y, b.z, acc[1][2]); acc[1][3] = fmaf(a.y, b.w, acc[1][3]);
            acc[2][0] = fmaf(a.z, b.x, acc[2][0]); acc[2][1] = fmaf(a.z, b.y, acc[2][1]);
            acc[2][2] = fmaf(a.z, b.z, acc[2][2]); acc[2][3] = fmaf(a.z, b.w, acc[2][3]);
            acc[3][0] = fmaf(a.w, b.x, acc[3][0]); acc[3][1] = fmaf(a.w, b.y, acc[3][1]);
            acc[3][2] = fmaf(a.w, b.z, acc[3][2]); acc[3][3] = fmaf(a.w, b.w, acc[3][3]);
        }
        __syncthreads();
    }
    #pragma unroll
    for (int m = 0; m < 4; ++m) {
        int row = (ty << 2) + m;
        float4 v = make_float4(acc[m][0], acc[m][1], acc[m][2], acc[m][3]);
        *(float4*)&P[((size_t)blockIdx.y * Bn + row) * N + n0 + (tx << 2)] = v;
    }
}

// ---------------------------------------------------------------------------
// fc1 split-reduce + bias + LN + relu -> g_h1
// ---------------------------------------------------------------------------
__global__ __launch_bounds__(256) void lnact1(
    const float* __restrict__ bias,
    const float* __restrict__ gamma, const float* __restrict__ beta)
{
    const float* part = &g_mp1[0][0][0];
    const int row = blockIdx.x;
    __shared__ float vbuf[512];
    float s = 0.f, ss = 0.f;
    for (int i = threadIdx.x; i < 512; i += 256) {
        float v = bias[i];
        #pragma unroll 8
        for (int sp = 0; sp < 32; ++sp)
            v += part[((size_t)sp * Bn + row) * 512 + i];
        vbuf[i] = v; s += v; ss += v * v;
    }
    __shared__ float rs[256], rq[256];
    rs[threadIdx.x] = s; rq[threadIdx.x] = ss;
    __syncthreads();
    for (int off = 128; off > 0; off >>= 1) {
        if (threadIdx.x < off) {
            rs[threadIdx.x] += rs[threadIdx.x + off];
            rq[threadIdx.x] += rq[threadIdx.x + off];
        }
        __syncthreads();
    }
    float mean = rs[0] * (1.f / 512);
    float var  = rq[0] * (1.f / 512) - mean * mean;
    float inv  = rsqrtf(var + 1e-5f);
    for (int i = threadIdx.x; i < 512; i += 256) {
        float v = (vbuf[i] - mean) * inv * gamma[i] + beta[i];
        g_h1[row * 512 + i] = fmaxf(v, 0.f);
    }
}

// ---------------------------------------------------------------------------
// Fused MLP tail: fc2 + LN + relu + fc3 + LN + tanh -> g_o. grid 32 x 256.
// ---------------------------------------------------------------------------
__global__ __launch_bounds__(256) void mlp_tail(
    const float* __restrict__ fc2_w, const float* __restrict__ fc2_b,
    const float* __restrict__ ln2_g, const float* __restrict__ ln2_b,
    const float* __restrict__ fc3_w, const float* __restrict__ fc3_b,
    const float* __restrict__ lno_g, const float* __restrict__ lno_b)
{
    const int row = blockIdx.x;
    const int t = threadIdx.x;
    const int lane = t & 31, wid = t >> 5;
    __shared__ float h1s[512], h2s[256], obuf[64];
    __shared__ float rs[8], rq[8], red3[4][64], stats[2];

    for (int i = t; i < 512; i += 256) h1s[i] = g_h1[row * 512 + i];
    __syncthreads();

    // fc2: column t, 4 accumulators to break the chain
    float a0 = 0.f, a1 = 0.f, a2 = 0.f, a3 = 0.f;
    #pragma unroll 4
    for (int k = 0; k < 512; k += 4) {
        a0 = fmaf(h1s[k + 0], fc2_w[(k + 0) * 256 + t], a0);
        a1 = fmaf(h1s[k + 1], fc2_w[(k + 1) * 256 + t], a1);
        a2 = fmaf(h1s[k + 2], fc2_w[(k + 2) * 256 + t], a2);
        a3 = fmaf(h1s[k + 3], fc2_w[(k + 3) * 256 + t], a3);
    }
    float v = fc2_b[t] + (a0 + a1) + (a2 + a3);

    // LN over 256 (one value per thread)
    float s = v, q = v * v;
    #pragma unroll
    for (int off = 16; off > 0; off >>= 1) {
        s += __shfl_down_sync(0xFFFFFFFF, s, off);
        q += __shfl_down_sync(0xFFFFFFFF, q, off);
    }
    if (lane == 0) { rs[wid] = s; rq[wid] = q; }
    __syncthreads();
    if (t == 0) {
        float S = 0.f, Q = 0.f;
        #pragma unroll
        for (int w = 0; w < 8; ++w) { S += rs[w]; Q += rq[w]; }
        float mean = S * (1.f / 256);
        stats[0] = mean;
        stats[1] = rsqrtf(Q * (1.f / 256) - mean * mean + 1e-5f);
    }
    __syncthreads();
    h2s[t] = fmaxf((v - stats[0]) * stats[1] * ln2_g[t] + ln2_b[t], 0.f);
    __syncthreads();

    // fc3: output n = t&63, k-slice = t>>6
    {
        int n = t & 63, sl = t >> 6;
        float p = 0.f;
        #pragma unroll 8
        for (int k = sl * 64; k < sl * 64 + 64; ++k)
            p = fmaf(h2s[k], fc3_w[k * 64 + n], p);
        red3[sl][n] = p;
    }
    __syncthreads();
    if (t < 64)
        obuf[t] = fc3_b[t] + (red3[0][t] + red3[1][t]) + (red3[2][t] + red3[3][t]);
    __syncthreads();

    // LN over 64 + tanh
    float o = (t < 64) ? obuf[t] : 0.f;
    float s2 = o, q2 = o * o;
    #pragma unroll
    for (int off = 16; off > 0; off >>= 1) {
        s2 += __shfl_down_sync(0xFFFFFFFF, s2, off);
        q2 += __shfl_down_sync(0xFFFFFFFF, q2, off);
    }
    if (lane == 0 && wid < 2) { rs[wid] = s2; rq[wid] = q2; }
    __syncthreads();
    if (t == 0) {
        float S = rs[0] + rs[1], Q = rq[0] + rq[1];
        float mean = S * (1.f / 64);
        stats[0] = mean;
        stats[1] = rsqrtf(Q * (1.f / 64) - mean * mean + 1e-5f);
    }
    __syncthreads();
    if (t < 64)
        g_o[row * 64 + t] = tanhf((o - stats[0]) * stats[1] * lno_g[t] + lno_b[t]);
}

// ---------------------------------------------------------------------------
__global__ __launch_bounds__(256) void alpha_kernel()
{
    __shared__ float dsh[Un];
    int t = threadIdx.x;
    if (t < Un) {
        float s = 0.f;
        #pragma unroll
        for (int b = 0; b < Bn; b++) s += g_o[b * Un + t];
        dsh[t] = s * (9.9f / (float)Bn);
    }
    __syncthreads();
    for (int d = t; d < Dn; d += 256) g_alpha[d] = dsh[d >> 6];
}

// ---------------------------------------------------------------------------
// Update: 64(i) x 128(j) tile, 4x8 micro-tile, f32x2 math.
// ---------------------------------------------------------------------------
__global__ __launch_bounds__(256) void update_kernel(
    const float* __restrict__ stim, const float* __restrict__ prev,
    const float* __restrict__ Wh, const float* __restrict__ Wr,
    const float* __restrict__ decay, float* __restrict__ out)
{
    const int mat = blockIdx.z;
    const float* __restrict__ A = mat ? prev : stim;
    const float* __restrict__ C = g_act[mat];
    const float* __restrict__ W = mat ? Wr : Wh;
    float* __restrict__ O = out + (size_t)(Bn + mat * Dn) * Dn;
    const int i0 = blockIdx.y * 64;
    const int j0 = blockIdx.x * 128;

    __shared__ float As[32][64];
    __shared__ float Cs[32][128];
    __shared__ float red[64][17];

    const int tid = threadIdx.x;
    #pragma unroll
    for (int r = 0; r < 2; ++r) {
        int idx = tid + r * 256;              // 512 float4
        int b = idx >> 4, c = (idx & 15) << 2;
        *(float4*)&As[b][c] = *(const float4*)&A[b * Dn + i0 + c];
    }
    #pragma unroll
    for (int r = 0; r < 4; ++r) {
        int idx = tid + r * 256;              // 1024 float4
        int b = idx >> 5, c = (idx & 31) << 2;
        *(float4*)&Cs[b][c] = *(const float4*)&C[b * Dn + j0 + c];
    }
    __syncthreads();

    const int tx = tid & 15, ty = tid >> 4;   // j: tx*8, i: ty*4
    unsigned long long acc2[4][4] = {};
    #pragma unroll
    for (int b = 0; b < 32; b++) {
        float4 a4 = *(const float4*)&As[b][ty * 4];
        ulonglong2 c01 = *(const ulonglong2*)&Cs[b][tx * 8];
        ulonglong2 c23 = *(const ulonglong2*)&Cs[b][tx * 8 + 4];
        unsigned long long am;
        PACK2(am, a4.x, a4.x);
        FMA2(acc2[0][0], am, c01.x); FMA2(acc2[0][1], am, c01.y);
        FMA2(acc2[0][2], am, c23.x); FMA2(acc2[0][3], am, c23.y);
        PACK2(am, a4.y, a4.y);
        FMA2(acc2[1][0], am, c01.x); FMA2(acc2[1][1], am, c01.y);
        FMA2(acc2[1][2], am, c23.x); FMA2(acc2[1][3], am, c23.y);
        PACK2(am, a4.z, a4.z);
        FMA2(acc2[2][0], am, c01.x); FMA2(acc2[2][1], am, c01.y);
        FMA2(acc2[2][2], am, c23.x); FMA2(acc2[2][3], am, c23.y);
        PACK2(am, a4.w, a4.w);
        FMA2(acc2[3][0], am, c01.x); FMA2(acc2[3][1], am, c01.y);
        FMA2(acc2[3][2], am, c23.x); FMA2(acc2[3][3], am, c23.y);
    }

    float al[8];
    *(float4*)&al[0] = *(const float4*)&g_alpha[j0 + tx * 8];
    *(float4*)&al[4] = *(const float4*)&g_alpha[j0 + tx * 8 + 4];
    #pragma unroll
    for (int m = 0; m < 4; m++) {
        int i = i0 + ty * 4 + m;
        float dm = 1.0f - decay[i];
        float wv[8];
        *(float4*)&wv[0] = *(const float4*)&W[(size_t)i * Dn + j0 + tx * 8];
        *(float4*)&wv[4] = *(const float4*)&W[(size_t)i * Dn + j0 + tx * 8 + 4];
        float ac[8];
        UNPK2(ac[0], ac[1], acc2[m][0]);
        UNPK2(ac[2], ac[3], acc2[m][1]);
        UNPK2(ac[4], ac[5], acc2[m][2]);
        UNPK2(ac[6], ac[7], acc2[m][3]);
        float v[8], ssum = 0.f;
        #pragma unroll
        for (int n = 0; n < 8; n++) {
            v[n] = (wv[n] + ac[n] * al[n]) * dm;
            ssum = fmaf(v[n], v[n], ssum);
        }
        *(float4*)&O[(size_t)i * Dn + j0 + tx * 8]     = *(float4*)&v[0];
        *(float4*)&O[(size_t)i * Dn + j0 + tx * 8 + 4] = *(float4*)&v[4];
        red[ty * 4 + m][tx] = ssum;
    }
    __syncthreads();
    if (tid < 64) {
        float s = 0.f;
        #pragma unroll
        for (int c = 0; c < 16; c++) s += red[tid][c];
        g_part[mat][blockIdx.x][i0 + tid] = s;
    }
}

// ---------------------------------------------------------------------------
__global__ __launch_bounds__(256) void norm_reduce_kernel()
{
    int mat = blockIdx.y;
    int i = blockIdx.x * 256 + threadIdx.x;
    float s = 0.f;
    #pragma unroll 8
    for (int jb = 0; jb < 32; jb++) s += g_part[mat][jb][i];
    g_norm[mat][i] = s;
}

// ---------------------------------------------------------------------------
__global__ __launch_bounds__(256) void scale_kernel(float* __restrict__ out)
{
    float4* base = (float4*)(out + (size_t)Bn * Dn);
    int t0 = blockIdx.x * 1024 + threadIdx.x;
    #pragma unroll
    for (int r = 0; r < 4; r++) {
        int idx = t0 + r * 256;
        size_t e = (size_t)idx << 2;
        int mat = (int)(e >> 24);
        int i = (int)((e >> 12) & (Dn - 1));
        float sc = 1.0f / fmaxf(sqrtf(g_norm[mat][i]), 1e-12f);
        float4 v = base[idx];
        v.x *= sc; v.y *= sc; v.z *= sc; v.w *= sc;
        base[idx] = v;
    }
}

// ---------------------------------------------------------------------------
extern "C" void kernel_launch(void* const* d_in, const int* in_sizes, int n_in,
                              void* d_out, int out_size)
{
    const float* stimulus = (const float*)d_in[0];
    const float* prev_act = (const float*)d_in[1];
    const float* W_heb    = (const float*)d_in[2];
    const float* W_rec    = (const float*)d_in[3];
    const float* decay    = (const float*)d_in[4];
    const float* ln_rec_g = (const float*)d_in[5];
    const float* ln_rec_b = (const float*)d_in[6];
    const float* fc1_w    = (const float*)d_in[7];
    const float* fc1_b    = (const float*)d_in[8];
    const float* ln1_g    = (const float*)d_in[9];
    const float* ln1_b    = (const float*)d_in[10];
    const float* fc2_w    = (const float*)d_in[11];
    const float* fc2_b    = (const float*)d_in[12];
    const float* ln2_g    = (const float*)d_in[13];
    const float* ln2_b    = (const float*)d_in[14];
    const float* fc3_w    = (const float*)d_in[15];
    const float* fc3_b    = (const float*)d_in[16];
    const float* lno_g    = (const float*)d_in[17];
    const float* lno_b    = (const float*)d_in[18];
    float* out = (float*)d_out;

    prep_x<<<dim3(512, 2), 256>>>(stimulus, prev_act);
    fwd_mma2<<<dim3(64, 4, 2), 128>>>(W_heb, W_rec);
    lnfinal_fused<<<32, 1024>>>(ln_rec_g, ln_rec_b, out);
    mlp_gemm2<<<dim3(4, 32), 256>>>(out, fc1_w, 4096, 512, 128);
    lnact1<<<32, 256>>>(fc1_b, ln1_g, ln1_b);
    mlp_tail<<<32, 256>>>(fc2_w, fc2_b, ln2_g, ln2_b, fc3_w, fc3_b, lno_g, lno_b);
    alpha_kernel<<<1, 256>>>();
    update_kernel<<<dim3(32, 64, 2), 256>>>(stimulus, prev_act, W_heb, W_rec, decay, out);
    norm_reduce_kernel<<<dim3(16, 2), 256>>>();
    scale_kernel<<<8192, 256>>>(out);
}

// round 8
// speedup vs baseline: 1.6636x; 1.0130x over previous
#include <cuda_runtime.h>
#include <cuda_bf16.h>
#include <math.h>
#include <stdint.h>

#define Dn 4096
#define Bn 32
#define Un 64

__device__ __nv_bfloat16 g_xsp[2][64][Dn];  // rows 0-31 hi(X), 32-63 lo(X)
__device__ float g_fpart[4][2][Bn][Dn];     // fwd split-K partials
__device__ float g_act[2][Bn * Dn];
__device__ float g_mp1[64][Bn][512];
__device__ float g_h1[Bn * 512];
__device__ float g_o[Bn * Un];
__device__ float g_alpha[Dn];
__device__ float g_dm[Dn];                  // 1 - decay
__device__ float g_part[2][32][Dn];

#define PACK2(v, lo, hi) asm("mov.b64 %0, {%1, %2};" : "=l"(v) : "f"(lo), "f"(hi))
#define UNPK2(lo, hi, v) asm("mov.b64 {%0, %1}, %2;" : "=f"(lo), "=f"(hi) : "l"(v))
#define FMA2(d, a, b) asm("fma.rn.f32x2 %0, %1, %2, %0;" : "+l"(d) : "l"(a), "l"(b))

__device__ __forceinline__ uint32_t smem_u32(const void* p) {
    uint32_t a;
    asm("{ .reg .u64 t; cvta.to.shared.u64 t, %1; cvt.u32.u64 %0, t; }" : "=r"(a) : "l"(p));
    return a;
}
__device__ __forceinline__ uint32_t pack_hi(float f0, float f1) {
    return (uint32_t)__bfloat16_as_ushort(__float2bfloat16(f0))
         | ((uint32_t)__bfloat16_as_ushort(__float2bfloat16(f1)) << 16);
}
__device__ __forceinline__ uint32_t pack_lo(float f0, float f1) {
    float r0 = f0 - __bfloat162float(__float2bfloat16(f0));
    float r1 = f1 - __bfloat162float(__float2bfloat16(f1));
    return pack_hi(r0, r1);
}
__device__ __forceinline__ void mma16816(float* d, const uint32_t* a,
                                         uint32_t b0, uint32_t b1) {
    asm volatile(
        "mma.sync.aligned.m16n8k16.row.col.f32.bf16.bf16.f32 "
        "{%0,%1,%2,%3}, {%4,%5,%6,%7}, {%8,%9}, {%0,%1,%2,%3};"
        : "+f"(d[0]), "+f"(d[1]), "+f"(d[2]), "+f"(d[3])
        : "r"(a[0]), "r"(a[1]), "r"(a[2]), "r"(a[3]), "r"(b0), "r"(b1));
}
#define LDSM_X4(r, p) \
    asm volatile("ldmatrix.sync.aligned.m8n8.x4.shared.b16 {%0,%1,%2,%3}, [%4];" \
        : "=r"((r)[0]), "=r"((r)[1]), "=r"((r)[2]), "=r"((r)[3]) : "r"(p))
#define LDSM_X4T(r, p) \
    asm volatile("ldmatrix.sync.aligned.m8n8.x4.trans.shared.b16 {%0,%1,%2,%3}, [%4];" \
        : "=r"((r)[0]), "=r"((r)[1]), "=r"((r)[2]), "=r"((r)[3]) : "r"(p))

// ---------------------------------------------------------------------------
__global__ __launch_bounds__(256) void prep_x1(const float* __restrict__ X, int mat)
{
    int idx = blockIdx.x * 256 + threadIdx.x;
    float x = X[idx];
    __nv_bfloat16 hi = __float2bfloat16(x);
    __nv_bfloat16 lo = __float2bfloat16(x - __bfloat162float(hi));
    int b = idx >> 12, d = idx & 4095;
    g_xsp[mat][b][d] = hi;
    g_xsp[mat][b + 32][d] = lo;
}

// ---------------------------------------------------------------------------
__global__ __launch_bounds__(256) void decay_prep(const float* __restrict__ decay)
{
    int i = blockIdx.x * 256 + threadIdx.x;
    g_dm[i] = 1.0f - decay[i];
}

// ---------------------------------------------------------------------------
// fwd via mma.sync bf16 hi/lo, coalesced W staging + ldmatrix.trans.
// ---------------------------------------------------------------------------
__global__ __launch_bounds__(128) void fwd_mma2(
    const float* __restrict__ Wh, const float* __restrict__ Wr)
{
    const int mat = blockIdx.z;
    const float* __restrict__ W = mat ? Wr : Wh;
    const int n0 = blockIdx.x * 64;
    const int kbase = blockIdx.y * 1024;

    __shared__ __nv_bfloat16 As[64][72];
    __shared__ __nv_bfloat16 Bh[64][72];
    __shared__ __nv_bfloat16 Bl[64][72];

    const int tid = threadIdx.x;
    const int lane = tid & 31;
    const int wid = tid >> 5;
    const int nloc = wid << 4;

    const int lsub = lane >> 3;
    const int arow = (lane & 7) + ((lsub & 1) << 3);
    const int acol = (lsub & 2) << 2;
    const int brow = (lane & 7) + ((lane & 8) ? 8 : 0);
    const int bcol = nloc + ((lane & 16) ? 8 : 0);

    float d[4][2][4] = {};
    uint4 areg[4];
    float4 wreg[8];

    {
        const int k0 = kbase;
        #pragma unroll
        for (int r = 0; r < 4; ++r) {
            int idx = tid + r * 128;
            areg[r] = *(const uint4*)&g_xsp[mat][idx >> 3][k0 + (idx & 7) * 8];
        }
        #pragma unroll
        for (int r = 0; r < 8; ++r) {
            int idx = tid + r * 128;
            wreg[r] = *(const float4*)&W[(size_t)(k0 + (idx >> 4)) * Dn + n0 + (idx & 15) * 4];
        }
    }

    for (int c = 0; c < 16; ++c) {
        #pragma unroll
        for (int r = 0; r < 4; ++r) {
            int idx = tid + r * 128;
            *(uint4*)&As[idx >> 3][(idx & 7) * 8] = areg[r];
        }
        #pragma unroll
        for (int r = 0; r < 8; ++r) {
            int idx = tid + r * 128;
            int row = idx >> 4, col = (idx & 15) * 4;
            float4 w = wreg[r];
            uint32_t h0 = pack_hi(w.x, w.y), h1 = pack_hi(w.z, w.w);
            uint32_t l0 = pack_lo(w.x, w.y), l1 = pack_lo(w.z, w.w);
            asm volatile("st.shared.v2.b32 [%0], {%1,%2};"
                :: "r"(smem_u32(&Bh[row][col])), "r"(h0), "r"(h1) : "memory");
            asm volatile("st.shared.v2.b32 [%0], {%1,%2};"
                :: "r"(smem_u32(&Bl[row][col])), "r"(l0), "r"(l1) : "memory");
        }
        __syncthreads();
        if (c < 15) {
            const int k0 = kbase + (c + 1) * 64;
            #pragma unroll
            for (int r = 0; r < 4; ++r) {
                int idx = tid + r * 128;
                areg[r] = *(const uint4*)&g_xsp[mat][idx >> 3][k0 + (idx & 7) * 8];
            }
            #pragma unroll
            for (int r = 0; r < 8; ++r) {
                int idx = tid + r * 128;
                wreg[r] = *(const float4*)&W[(size_t)(k0 + (idx >> 4)) * Dn + n0 + (idx & 15) * 4];
            }
        }
        #pragma unroll
        for (int kk = 0; kk < 4; ++kk) {
            uint32_t bh[4], bl[4];
            LDSM_X4T(bh, smem_u32(&Bh[kk * 16 + brow][bcol]));
            LDSM_X4T(bl, smem_u32(&Bl[kk * 16 + brow][bcol]));
            #pragma unroll
            for (int mt = 0; mt < 4; ++mt) {
                uint32_t a[4];
                LDSM_X4(a, smem_u32(&As[mt * 16 + arow][kk * 16 + acol]));
                mma16816(d[mt][0], a, bh[0], bh[1]);
                mma16816(d[mt][1], a, bh[2], bh[3]);
                mma16816(d[mt][0], a, bl[0], bl[1]);
                mma16816(d[mt][1], a, bl[2], bl[3]);
            }
        }
        __syncthreads();
    }

    float* P = &g_fpart[blockIdx.y][mat][0][0];
    const int g = lane >> 2, cc = (lane & 3) * 2;
    #pragma unroll
    for (int h = 0; h < 2; ++h) {
        #pragma unroll
        for (int j = 0; j < 2; ++j) {
            float v0 = d[h][j][0] + d[h + 2][j][0];
            float v1 = d[h][j][1] + d[h + 2][j][1];
            float v2 = d[h][j][2] + d[h + 2][j][2];
            float v3 = d[h][j][3] + d[h + 2][j][3];
            int r0 = h * 16 + g;
            int col = n0 + nloc + j * 8 + cc;
            *(float2*)&P[r0 * Dn + col] = make_float2(v0, v1);
            *(float2*)&P[(r0 + 8) * Dn + col] = make_float2(v2, v3);
        }
    }
}

// ---------------------------------------------------------------------------
__global__ __launch_bounds__(1024) void lnfinal_fused(
    const float* __restrict__ gamma, const float* __restrict__ beta,
    float* __restrict__ out)
{
    const int row = blockIdx.x;
    const int t = threadIdx.x;
    const int lane = t & 31, wid = t >> 5;
    const float4* fp = (const float4*)&g_fpart[0][0][0][0];

    float4 a = fp[(size_t)(0 * 32 + row) * 1024 + t];
    #pragma unroll
    for (int s = 1; s < 4; ++s) {
        float4 b = fp[(size_t)((s * 2 + 0) * 32 + row) * 1024 + t];
        a.x += b.x; a.y += b.y; a.z += b.z; a.w += b.w;
    }
    float4 stim = make_float4(fmaxf(a.x, 0.f), fmaxf(a.y, 0.f),
                              fmaxf(a.z, 0.f), fmaxf(a.w, 0.f));
    ((float4*)&g_act[0][row * Dn])[t] = stim;

    a = fp[(size_t)(1 * 32 + row) * 1024 + t];
    #pragma unroll
    for (int s = 1; s < 4; ++s) {
        float4 b = fp[(size_t)((s * 2 + 1) * 32 + row) * 1024 + t];
        a.x += b.x; a.y += b.y; a.z += b.z; a.w += b.w;
    }
    float4 rec = make_float4(fmaxf(a.x, 0.f), fmaxf(a.y, 0.f),
                             fmaxf(a.z, 0.f), fmaxf(a.w, 0.f));
    ((float4*)&g_act[1][row * Dn])[t] = rec;

    float s = rec.x + rec.y + rec.z + rec.w;
    float q = rec.x * rec.x + rec.y * rec.y + rec.z * rec.z + rec.w * rec.w;
    #pragma unroll
    for (int off = 16; off > 0; off >>= 1) {
        s += __shfl_down_sync(0xFFFFFFFF, s, off);
        q += __shfl_down_sync(0xFFFFFFFF, q, off);
    }
    __shared__ float rs[32], rq[32], stats[2];
    if (lane == 0) { rs[wid] = s; rq[wid] = q; }
    __syncthreads();
    if (wid == 0) {
        s = rs[lane]; q = rq[lane];
        #pragma unroll
        for (int off = 16; off > 0; off >>= 1) {
            s += __shfl_down_sync(0xFFFFFFFF, s, off);
            q += __shfl_down_sync(0xFFFFFFFF, q, off);
        }
        if (lane == 0) {
            float mean = s * (1.f / Dn);
            float var = q * (1.f / Dn) - mean * mean;
            stats[0] = mean;
            stats[1] = rsqrtf(var + 1e-5f);
        }
    }
    __syncthreads();
    float mean = stats[0], inv = stats[1];
    float4 gm = ((const float4*)gamma)[t];
    float4 bt = ((const float4*)beta)[t];
    float4 o;
    o.x = (rec.x - mean) * inv * gm.x + bt.x + stim.x;
    o.y = (rec.y - mean) * inv * gm.y + bt.y + stim.y;
    o.z = (rec.z - mean) * inv * gm.z + bt.z + stim.z;
    o.w = (rec.w - mean) * inv * gm.w + bt.w + stim.w;
    ((float4*)&out[row * Dn])[t] = o;
}

// ---------------------------------------------------------------------------
__global__ __launch_bounds__(256) void mlp_gemm2(
    const float* __restrict__ X, const float* __restrict__ W, int K, int N, int Kc)
{
    float* __restrict__ P = &g_mp1[0][0][0];
    const int n0 = blockIdx.x * 128;
    const int kbase = blockIdx.y * Kc;
    const int iters = Kc >> 5;

    __shared__ float Xs[32][36];
    __shared__ float Ws[32][128];
    const int tid = threadIdx.x;
    const int xrow = tid >> 3, xk = (tid & 7) << 2;
    const int wk = tid >> 5, wn = (tid & 31) << 2;
    const int tx = tid & 31, ty = tid >> 5;

    float4 xr  = *(const float4*)&X[xrow * K + kbase + xk];
    float4 wr0 = *(const float4*)&W[(size_t)(kbase + wk +  0) * N + n0 + wn];
    float4 wr1 = *(const float4*)&W[(size_t)(kbase + wk +  8) * N + n0 + wn];
    float4 wr2 = *(const float4*)&W[(size_t)(kbase + wk + 16) * N + n0 + wn];
    float4 wr3 = *(const float4*)&W[(size_t)(kbase + wk + 24) * N + n0 + wn];
    float acc[4][4] = {};

    for (int c = 0; c < iters; ++c) {
        Xs[xk + 0][xrow] = xr.x; Xs[xk + 1][xrow] = xr.y;
        Xs[xk + 2][xrow] = xr.z; Xs[xk + 3][xrow] = xr.w;
        *(float4*)&Ws[wk +  0][wn] = wr0;
        *(float4*)&Ws[wk +  8][wn] = wr1;
        *(float4*)&Ws[wk + 16][wn] = wr2;
        *(float4*)&Ws[wk + 24][wn] = wr3;
        __syncthreads();
        if (c + 1 < iters) {
            int k = kbase + (c + 1) * 32;
            xr  = *(const float4*)&X[xrow * K + k + xk];
            wr0 = *(const float4*)&W[(size_t)(k + wk +  0) * N + n0 + wn];
            wr1 = *(const float4*)&W[(size_t)(k + wk +  8) * N + n0 + wn];
            wr2 = *(const float4*)&W[(size_t)(k + wk + 16) * N + n0 + wn];
            wr3 = *(const float4*)&W[(size_t)(k + wk + 24) * N + n0 + wn];
        }
        #pragma unroll 8
        for (int kk = 0; kk < 32; ++kk) {
            float4 a = *(const float4*)&Xs[kk][ty << 2];
            float4 b = *(const float4*)&Ws[kk][tx << 2];
            acc[0][0] = fmaf(a.x, b.x, acc[0][0]); acc[0][1] = fmaf(a.x, b.y, acc[0][1]);
            acc[0][2] = fmaf(a.x, b.z, acc[0][2]); acc[0][3] = fmaf(a.x, b.w, acc[0][3]);
            acc[1][0] = fmaf(a.y, b.x, acc[1][0]); acc[1][1] = fmaf(a.y, b.y, acc[1][1]);
            acc[1][2] = fmaf(a.y, b.z, acc[1][2]); acc[1][3] = fmaf(a.y, b.w, acc[1][3]);
            acc[2][0] = fmaf(a.z, b.x, acc[2][0]); acc[2][1] = fmaf(a.z, b.y, acc[2][1]);
            acc[2][2] = fmaf(a.z, b.z, acc[2][2]); acc[2][3] = fmaf(a.z, b.w, acc[2][3]);
            acc[3][0] = fmaf(a.w, b.x, acc[3][0]); acc[3][1] = fmaf(a.w, b.y, acc[3][1]);
            acc[3][2] = fmaf(a.w, b.z, acc[3][2]); acc[3][3] = fmaf(a.w, b.w, acc[3][3]);
        }
        __syncthreads();
    }
    #pragma unroll
    for (int m = 0; m < 4; ++m) {
        int row = (ty << 2) + m;
        float4 v = make_float4(acc[m][0], acc[m][1], acc[m][2], acc[m][3]);
        *(float4*)&P[((size_t)blockIdx.y * Bn + row) * N + n0 + (tx << 2)] = v;
    }
}

// ---------------------------------------------------------------------------
__global__ __launch_bounds__(256) void lnact1(
    const float* __restrict__ bias,
    const float* __restrict__ gamma, const float* __restrict__ beta)
{
    const float* part = &g_mp1[0][0][0];
    const int row = blockIdx.x;
    __shared__ float vbuf[512];
    float s = 0.f, ss = 0.f;
    for (int i = threadIdx.x; i < 512; i += 256) {
        float v = bias[i];
        #pragma unroll 8
        for (int sp = 0; sp < 64; ++sp)
            v += part[((size_t)sp * Bn + row) * 512 + i];
        vbuf[i] = v; s += v; ss += v * v;
    }
    __shared__ float rs[256], rq[256];
    rs[threadIdx.x] = s; rq[threadIdx.x] = ss;
    __syncthreads();
    for (int off = 128; off > 0; off >>= 1) {
        if (threadIdx.x < off) {
            rs[threadIdx.x] += rs[threadIdx.x + off];
            rq[threadIdx.x] += rq[threadIdx.x + off];
        }
        __syncthreads();
    }
    float mean = rs[0] * (1.f / 512);
    float var  = rq[0] * (1.f / 512) - mean * mean;
    float inv  = rsqrtf(var + 1e-5f);
    for (int i = threadIdx.x; i < 512; i += 256) {
        float v = (vbuf[i] - mean) * inv * gamma[i] + beta[i];
        g_h1[row * 512 + i] = fmaxf(v, 0.f);
    }
}

// ---------------------------------------------------------------------------
__global__ __launch_bounds__(256) void mlp_tail(
    const float* __restrict__ fc2_w, const float* __restrict__ fc2_b,
    const float* __restrict__ ln2_g, const float* __restrict__ ln2_b,
    const float* __restrict__ fc3_w, const float* __restrict__ fc3_b,
    const float* __restrict__ lno_g, const float* __restrict__ lno_b)
{
    const int row = blockIdx.x;
    const int t = threadIdx.x;
    const int lane = t & 31, wid = t >> 5;
    __shared__ float h1s[512], h2s[256], obuf[64];
    __shared__ float rs[8], rq[8], red3[4][64], stats[2];

    for (int i = t; i < 512; i += 256) h1s[i] = g_h1[row * 512 + i];
    __syncthreads();

    float a0 = 0.f, a1 = 0.f, a2 = 0.f, a3 = 0.f;
    #pragma unroll 4
    for (int k = 0; k < 512; k += 4) {
        a0 = fmaf(h1s[k + 0], fc2_w[(k + 0) * 256 + t], a0);
        a1 = fmaf(h1s[k + 1], fc2_w[(k + 1) * 256 + t], a1);
        a2 = fmaf(h1s[k + 2], fc2_w[(k + 2) * 256 + t], a2);
        a3 = fmaf(h1s[k + 3], fc2_w[(k + 3) * 256 + t], a3);
    }
    float v = fc2_b[t] + (a0 + a1) + (a2 + a3);

    float s = v, q = v * v;
    #pragma unroll
    for (int off = 16; off > 0; off >>= 1) {
        s += __shfl_down_sync(0xFFFFFFFF, s, off);
        q += __shfl_down_sync(0xFFFFFFFF, q, off);
    }
    if (lane == 0) { rs[wid] = s; rq[wid] = q; }
    __syncthreads();
    if (t == 0) {
        float S = 0.f, Q = 0.f;
        #pragma unroll
        for (int w = 0; w < 8; ++w) { S += rs[w]; Q += rq[w]; }
        float mean = S * (1.f / 256);
        stats[0] = mean;
        stats[1] = rsqrtf(Q * (1.f / 256) - mean * mean + 1e-5f);
    }
    __syncthreads();
    h2s[t] = fmaxf((v - stats[0]) * stats[1] * ln2_g[t] + ln2_b[t], 0.f);
    __syncthreads();

    {
        int n = t & 63, sl = t >> 6;
        float p = 0.f;
        #pragma unroll 8
        for (int k = sl * 64; k < sl * 64 + 64; ++k)
            p = fmaf(h2s[k], fc3_w[k * 64 + n], p);
        red3[sl][n] = p;
    }
    __syncthreads();
    if (t < 64)
        obuf[t] = fc3_b[t] + (red3[0][t] + red3[1][t]) + (red3[2][t] + red3[3][t]);
    __syncthreads();

    float o = (t < 64) ? obuf[t] : 0.f;
    float s2 = o, q2 = o * o;
    #pragma unroll
    for (int off = 16; off > 0; off >>= 1) {
        s2 += __shfl_down_sync(0xFFFFFFFF, s2, off);
        q2 += __shfl_down_sync(0xFFFFFFFF, q2, off);
    }
    if (lane == 0 && wid < 2) { rs[wid] = s2; rq[wid] = q2; }
    __syncthreads();
    if (t == 0) {
        float S = rs[0] + rs[1], Q = rq[0] + rq[1];
        float mean = S * (1.f / 64);
        stats[0] = mean;
        stats[1] = rsqrtf(Q * (1.f / 64) - mean * mean + 1e-5f);
    }
    __syncthreads();
    if (t < 64)
        g_o[row * 64 + t] = tanhf((o - stats[0]) * stats[1] * lno_g[t] + lno_b[t]);
}

// ---------------------------------------------------------------------------
__global__ __launch_bounds__(256) void alpha_kernel()
{
    __shared__ float dsh[Un];
    int t = threadIdx.x;
    if (t < Un) {
        float s = 0.f;
        #pragma unroll
        for (int b = 0; b < Bn; b++) s += g_o[b * Un + t];
        dsh[t] = s * (9.9f / (float)Bn);
    }
    __syncthreads();
    for (int d = t; d < Dn; d += 256) g_alpha[d] = dsh[d >> 6];
}

// ---------------------------------------------------------------------------
// Update: 128(i) x 128(j) tile, 8x8 micro-tile, f32x2 math.
// ---------------------------------------------------------------------------
__global__ __launch_bounds__(256) void update_kernel(
    const float* __restrict__ stim, const float* __restrict__ prev,
    const float* __restrict__ Wh, const float* __restrict__ Wr,
    float* __restrict__ out)
{
    const int mat = blockIdx.z;
    const float* __restrict__ A = mat ? prev : stim;
    const float* __restrict__ C = g_act[mat];
    const float* __restrict__ W = mat ? Wr : Wh;
    float* __restrict__ O = out + (size_t)(Bn + mat * Dn) * Dn;
    const int i0 = blockIdx.y * 128;
    const int j0 = blockIdx.x * 128;

    __shared__ float As[32][128];
    __shared__ float Cs[32][128];
    __shared__ float red[128][17];

    const int tid = threadIdx.x;
    #pragma unroll
    for (int r = 0; r < 4; ++r) {
        int idx = tid + r * 256;              // 1024 float4 each
        int b = idx >> 5, c = (idx & 31) << 2;
        *(float4*)&As[b][c] = *(const float4*)&A[b * Dn + i0 + c];
        *(float4*)&Cs[b][c] = *(const float4*)&C[b * Dn + j0 + c];
    }
    __syncthreads();

    const int tx = tid & 15, ty = tid >> 4;   // j: tx*8, i: ty*8
    unsigned long long acc2[8][4] = {};
    #pragma unroll
    for (int b = 0; b < 32; b++) {
        float a8[8];
        *(float4*)&a8[0] = *(const float4*)&As[b][ty * 8];
        *(float4*)&a8[4] = *(const float4*)&As[b][ty * 8 + 4];
        ulonglong2 c01 = *(const ulonglong2*)&Cs[b][tx * 8];
        ulonglong2 c23 = *(const ulonglong2*)&Cs[b][tx * 8 + 4];
        #pragma unroll
        for (int m = 0; m < 8; ++m) {
            unsigned long long am;
            PACK2(am, a8[m], a8[m]);
            FMA2(acc2[m][0], am, c01.x); FMA2(acc2[m][1], am, c01.y);
            FMA2(acc2[m][2], am, c23.x); FMA2(acc2[m][3], am, c23.y);
        }
    }

    float al[8];
    *(float4*)&al[0] = *(const float4*)&g_alpha[j0 + tx * 8];
    *(float4*)&al[4] = *(const float4*)&g_alpha[j0 + tx * 8 + 4];
    #pragma unroll
    for (int m = 0; m < 8; m++) {
        int i = i0 + ty * 8 + m;
        float dm = g_dm[i];
        float wv[8];
        *(float4*)&wv[0] = *(const float4*)&W[(size_t)i * Dn + j0 + tx * 8];
        *(float4*)&wv[4] = *(const float4*)&W[(size_t)i * Dn + j0 + tx * 8 + 4];
        float ac[8];
        UNPK2(ac[0], ac[1], acc2[m][0]);
        UNPK2(ac[2], ac[3], acc2[m][1]);
        UNPK2(ac[4], ac[5], acc2[m][2]);
        UNPK2(ac[6], ac[7], acc2[m][3]);
        float v[8], ssum = 0.f;
        #pragma unroll
        for (int n = 0; n < 8; n++) {
            v[n] = (wv[n] + ac[n] * al[n]) * dm;
            ssum = fmaf(v[n], v[n], ssum);
        }
        *(float4*)&O[(size_t)i * Dn + j0 + tx * 8]     = *(float4*)&v[0];
        *(float4*)&O[(size_t)i * Dn + j0 + tx * 8 + 4] = *(float4*)&v[4];
        red[ty * 8 + m][tx] = ssum;
    }
    __syncthreads();
    if (tid < 128) {
        float s = 0.f;
        #pragma unroll
        for (int c = 0; c < 16; c++) s += red[tid][c];
        g_part[mat][blockIdx.x][i0 + tid] = s;
    }
}

// ---------------------------------------------------------------------------
// One CTA per row: inline norm reduce (32 j-block partials) + scale row.
// ---------------------------------------------------------------------------
__global__ __launch_bounds__(256) void scale_kernel(float* __restrict__ out)
{
    const int row = blockIdx.x;               // 0..8191
    const int mat = row >> 12, i = row & 4095;
    __shared__ float sinv;
    if (threadIdx.x < 32) {
        float p = g_part[mat][threadIdx.x][i];
        #pragma unroll
        for (int off = 16; off > 0; off >>= 1)
            p += __shfl_down_sync(0xFFFFFFFF, p, off);
        if (threadIdx.x == 0)
            sinv = 1.0f / fmaxf(sqrtf(p), 1e-12f);
    }
    __syncthreads();
    const float sc = sinv;
    float4* base = (float4*)(out + (size_t)Bn * Dn + (size_t)row * Dn);
    #pragma unroll
    for (int r = 0; r < 4; ++r) {
        int idx = threadIdx.x + r * 256;
        float4 v = base[idx];
        v.x *= sc; v.y *= sc; v.z *= sc; v.w *= sc;
        base[idx] = v;
    }
}

// ---------------------------------------------------------------------------
extern "C" void kernel_launch(void* const* d_in, const int* in_sizes, int n_in,
                              void* d_out, int out_size)
{
    const float* stimulus = (const float*)d_in[0];
    const float* prev_act = (const float*)d_in[1];
    const float* W_heb    = (const float*)d_in[2];
    const float* W_rec    = (const float*)d_in[3];
    const float* decay    = (const float*)d_in[4];
    const float* ln_rec_g = (const float*)d_in[5];
    const float* ln_rec_b = (const float*)d_in[6];
    const float* fc1_w    = (const float*)d_in[7];
    const float* fc1_b    = (const float*)d_in[8];
    const float* ln1_g    = (const float*)d_in[9];
    const float* ln1_b    = (const float*)d_in[10];
    const float* fc2_w    = (const float*)d_in[11];
    const float* fc2_b    = (const float*)d_in[12];
    const float* ln2_g    = (const float*)d_in[13];
    const float* ln2_b    = (const float*)d_in[14];
    const float* fc3_w    = (const float*)d_in[15];
    const float* fc3_b    = (const float*)d_in[16];
    const float* lno_g    = (const float*)d_in[17];
    const float* lno_b    = (const float*)d_in[18];
    float* out = (float*)d_out;

    prep_x1<<<512, 256>>>(stimulus, 0);                       // 1
    prep_x1<<<512, 256>>>(prev_act, 1);                       // 2
    decay_prep<<<16, 256>>>(decay);                           // 3
    fwd_mma2<<<dim3(64, 4, 2), 128>>>(W_heb, W_rec);          // 4 (ncu samples this)
    lnfinal_fused<<<32, 1024>>>(ln_rec_g, ln_rec_b, out);     // 5
    mlp_gemm2<<<dim3(4, 64), 256>>>(out, fc1_w, 4096, 512, 64); // 6
    lnact1<<<32, 256>>>(fc1_b, ln1_g, ln1_b);                 // 7
    mlp_tail<<<32, 256>>>(fc2_w, fc2_b, ln2_g, ln2_b, fc3_w, fc3_b, lno_g, lno_b); // 8
    alpha_kernel<<<1, 256>>>();                               // 9
    update_kernel<<<dim3(32, 32, 2), 256>>>(stimulus, prev_act, W_heb, W_rec, out); // 10
    scale_kernel<<<8192, 256>>>(out);                         // 11
}

// round 9
// speedup vs baseline: 1.6781x; 1.0088x over previous
#include <cuda_runtime.h>
#include <cuda_bf16.h>
#include <math.h>
#include <stdint.h>

#define Dn 4096
#define Bn 32
#define Un 64

__device__ __nv_bfloat16 g_xsp[2][64][Dn];  // rows 0-31 hi(X), 32-63 lo(X)
__device__ float g_fpart[4][2][Bn][Dn];     // fwd split-K partials
__device__ float g_act[2][Bn * Dn];
__device__ float g_mp1[32][Bn][512];
__device__ float g_h1[Bn * 512];
__device__ float g_o[Bn * Un];
__device__ float g_alpha[Dn];
__device__ float g_dm[Dn];                  // 1 - decay
__device__ float g_part[2][32][Dn];         // row sumsq partials (no dm factor)

#define PACK2(v, lo, hi) asm("mov.b64 %0, {%1, %2};" : "=l"(v) : "f"(lo), "f"(hi))
#define UNPK2(lo, hi, v) asm("mov.b64 {%0, %1}, %2;" : "=f"(lo), "=f"(hi) : "l"(v))
#define FMA2(d, a, b) asm("fma.rn.f32x2 %0, %1, %2, %0;" : "+l"(d) : "l"(a), "l"(b))

__device__ __forceinline__ uint32_t smem_u32(const void* p) {
    uint32_t a;
    asm("{ .reg .u64 t; cvta.to.shared.u64 t, %1; cvt.u32.u64 %0, t; }" : "=r"(a) : "l"(p));
    return a;
}
__device__ __forceinline__ uint32_t pack_hi(float f0, float f1) {
    return (uint32_t)__bfloat16_as_ushort(__float2bfloat16(f0))
         | ((uint32_t)__bfloat16_as_ushort(__float2bfloat16(f1)) << 16);
}
__device__ __forceinline__ uint32_t pack_lo(float f0, float f1) {
    float r0 = f0 - __bfloat162float(__float2bfloat16(f0));
    float r1 = f1 - __bfloat162float(__float2bfloat16(f1));
    return pack_hi(r0, r1);
}
__device__ __forceinline__ void mma16816(float* d, const uint32_t* a,
                                         uint32_t b0, uint32_t b1) {
    asm volatile(
        "mma.sync.aligned.m16n8k16.row.col.f32.bf16.bf16.f32 "
        "{%0,%1,%2,%3}, {%4,%5,%6,%7}, {%8,%9}, {%0,%1,%2,%3};"
        : "+f"(d[0]), "+f"(d[1]), "+f"(d[2]), "+f"(d[3])
        : "r"(a[0]), "r"(a[1]), "r"(a[2]), "r"(a[3]), "r"(b0), "r"(b1));
}
#define LDSM_X4(r, p) \
    asm volatile("ldmatrix.sync.aligned.m8n8.x4.shared.b16 {%0,%1,%2,%3}, [%4];" \
        : "=r"((r)[0]), "=r"((r)[1]), "=r"((r)[2]), "=r"((r)[3]) : "r"(p))
#define LDSM_X4T(r, p) \
    asm volatile("ldmatrix.sync.aligned.m8n8.x4.trans.shared.b16 {%0,%1,%2,%3}, [%4];" \
        : "=r"((r)[0]), "=r"((r)[1]), "=r"((r)[2]), "=r"((r)[3]) : "r"(p))
#define CP_ASYNC16(dst, src) \
    asm volatile("cp.async.ca.shared.global [%0], [%1], 16;" :: "r"(dst), "l"(src))
#define CP_COMMIT() asm volatile("cp.async.commit_group;" ::: "memory")
#define CP_WAIT(n)  asm volatile("cp.async.wait_group %0;" :: "n"(n) : "memory")

// ---------------------------------------------------------------------------
__global__ __launch_bounds__(256) void prep_x1(const float* __restrict__ X, int mat)
{
    int idx = blockIdx.x * 256 + threadIdx.x;
    float x = X[idx];
    __nv_bfloat16 hi = __float2bfloat16(x);
    __nv_bfloat16 lo = __float2bfloat16(x - __bfloat162float(hi));
    int b = idx >> 12, d = idx & 4095;
    g_xsp[mat][b][d] = hi;
    g_xsp[mat][b + 32][d] = lo;
}

// ---------------------------------------------------------------------------
__global__ __launch_bounds__(256) void decay_prep(const float* __restrict__ decay)
{
    int i = blockIdx.x * 256 + threadIdx.x;
    g_dm[i] = 1.0f - decay[i];
}

// ---------------------------------------------------------------------------
// fwd v3: 32-k chunks, cp.async A staging, register W prefetch (4 float4).
// grid (64 n, 4 splits, 2 mats), 128 threads.
// ---------------------------------------------------------------------------
__global__ __launch_bounds__(128) void fwd_mma3(
    const float* __restrict__ Wh, const float* __restrict__ Wr)
{
    const int mat = blockIdx.z;
    const float* __restrict__ W = mat ? Wr : Wh;
    const int n0 = blockIdx.x * 64;
    const int kbase = blockIdx.y * 1024;

    __shared__ __nv_bfloat16 As[2][64][40];   // [buf][m][k32], row 80B
    __shared__ __nv_bfloat16 Bh[32][72];
    __shared__ __nv_bfloat16 Bl[32][72];

    const int tid = threadIdx.x;
    const int lane = tid & 31;
    const int wid = tid >> 5;
    const int nloc = wid << 4;

    const int lsub = lane >> 3;
    const int arow = (lane & 7) + ((lsub & 1) << 3);
    const int acol = (lsub & 2) << 2;
    const int brow = (lane & 7) + ((lane & 8) ? 8 : 0);
    const int bcol = nloc + ((lane & 16) ? 8 : 0);

    // cp.async A chunk: 64 rows x 64B = 256 x 16B, 2 per thread
    const int ar0 = tid >> 1;              // rows tid/2 ... (two segs per thread)
    const int as0 = (tid & 1) << 1;        // seg 0/2 then +1

    float d[4][2][4] = {};
    float4 wreg[4];

    // prologue: A chunk 0, W chunk 0
    {
        #pragma unroll
        for (int r = 0; r < 2; ++r) {
            int seg = as0 + r;
            CP_ASYNC16(smem_u32(&As[0][ar0][seg * 8]),
                       (const void*)&g_xsp[mat][ar0][kbase + seg * 8]);
        }
        CP_COMMIT();
        #pragma unroll
        for (int r = 0; r < 4; ++r) {
            int idx = tid + r * 128;
            wreg[r] = *(const float4*)&W[(size_t)(kbase + (idx >> 4)) * Dn + n0 + (idx & 15) * 4];
        }
    }

    for (int c = 0; c < 32; ++c) {
        const int buf = c & 1;
        // convert current W regs -> Bh/Bl
        #pragma unroll
        for (int r = 0; r < 4; ++r) {
            int idx = tid + r * 128;
            int row = idx >> 4, col = (idx & 15) * 4;
            float4 w = wreg[r];
            uint32_t h0 = pack_hi(w.x, w.y), h1 = pack_hi(w.z, w.w);
            uint32_t l0 = pack_lo(w.x, w.y), l1 = pack_lo(w.z, w.w);
            asm volatile("st.shared.v2.b32 [%0], {%1,%2};"
                :: "r"(smem_u32(&Bh[row][col])), "r"(h0), "r"(h1) : "memory");
            asm volatile("st.shared.v2.b32 [%0], {%1,%2};"
                :: "r"(smem_u32(&Bl[row][col])), "r"(l0), "r"(l1) : "memory");
        }
        if (c < 31) {
            const int k1 = kbase + (c + 1) * 32;
            #pragma unroll
            for (int r = 0; r < 2; ++r) {
                int seg = as0 + r;
                CP_ASYNC16(smem_u32(&As[buf ^ 1][ar0][seg * 8]),
                           (const void*)&g_xsp[mat][ar0][k1 + seg * 8]);
            }
            CP_COMMIT();
            CP_WAIT(1);
        } else {
            CP_WAIT(0);
        }
        __syncthreads();
        if (c < 31) {
            const int k1 = kbase + (c + 1) * 32;
            #pragma unroll
            for (int r = 0; r < 4; ++r) {
                int idx = tid + r * 128;
                wreg[r] = *(const float4*)&W[(size_t)(k1 + (idx >> 4)) * Dn + n0 + (idx & 15) * 4];
            }
        }
        #pragma unroll
        for (int kk = 0; kk < 2; ++kk) {
            uint32_t bh[4], bl[4];
            LDSM_X4T(bh, smem_u32(&Bh[kk * 16 + brow][bcol]));
            LDSM_X4T(bl, smem_u32(&Bl[kk * 16 + brow][bcol]));
            #pragma unroll
            for (int mt = 0; mt < 4; ++mt) {
                uint32_t a[4];
                LDSM_X4(a, smem_u32(&As[buf][mt * 16 + arow][kk * 16 + acol]));
                mma16816(d[mt][0], a, bh[0], bh[1]);
                mma16816(d[mt][1], a, bh[2], bh[3]);
                mma16816(d[mt][0], a, bl[0], bl[1]);
                mma16816(d[mt][1], a, bl[2], bl[3]);
            }
        }
        __syncthreads();
    }

    float* P = &g_fpart[blockIdx.y][mat][0][0];
    const int g = lane >> 2, cc = (lane & 3) * 2;
    #pragma unroll
    for (int h = 0; h < 2; ++h) {
        #pragma unroll
        for (int j = 0; j < 2; ++j) {
            float v0 = d[h][j][0] + d[h + 2][j][0];
            float v1 = d[h][j][1] + d[h + 2][j][1];
            float v2 = d[h][j][2] + d[h + 2][j][2];
            float v3 = d[h][j][3] + d[h + 2][j][3];
            int r0 = h * 16 + g;
            int col = n0 + nloc + j * 8 + cc;
            *(float2*)&P[r0 * Dn + col] = make_float2(v0, v1);
            *(float2*)&P[(r0 + 8) * Dn + col] = make_float2(v2, v3);
        }
    }
}

// ---------------------------------------------------------------------------
__global__ __launch_bounds__(1024) void lnfinal_fused(
    const float* __restrict__ gamma, const float* __restrict__ beta,
    float* __restrict__ out)
{
    const int row = blockIdx.x;
    const int t = threadIdx.x;
    const int lane = t & 31, wid = t >> 5;
    const float4* fp = (const float4*)&g_fpart[0][0][0][0];

    float4 a = fp[(size_t)(0 * 32 + row) * 1024 + t];
    #pragma unroll
    for (int s = 1; s < 4; ++s) {
        float4 b = fp[(size_t)((s * 2 + 0) * 32 + row) * 1024 + t];
        a.x += b.x; a.y += b.y; a.z += b.z; a.w += b.w;
    }
    float4 stim = make_float4(fmaxf(a.x, 0.f), fmaxf(a.y, 0.f),
                              fmaxf(a.z, 0.f), fmaxf(a.w, 0.f));
    ((float4*)&g_act[0][row * Dn])[t] = stim;

    a = fp[(size_t)(1 * 32 + row) * 1024 + t];
    #pragma unroll
    for (int s = 1; s < 4; ++s) {
        float4 b = fp[(size_t)((s * 2 + 1) * 32 + row) * 1024 + t];
        a.x += b.x; a.y += b.y; a.z += b.z; a.w += b.w;
    }
    float4 rec = make_float4(fmaxf(a.x, 0.f), fmaxf(a.y, 0.f),
                             fmaxf(a.z, 0.f), fmaxf(a.w, 0.f));
    ((float4*)&g_act[1][row * Dn])[t] = rec;

    float s = rec.x + rec.y + rec.z + rec.w;
    float q = rec.x * rec.x + rec.y * rec.y + rec.z * rec.z + rec.w * rec.w;
    #pragma unroll
    for (int off = 16; off > 0; off >>= 1) {
        s += __shfl_down_sync(0xFFFFFFFF, s, off);
        q += __shfl_down_sync(0xFFFFFFFF, q, off);
    }
    __shared__ float rs[32], rq[32], stats[2];
    if (lane == 0) { rs[wid] = s; rq[wid] = q; }
    __syncthreads();
    if (wid == 0) {
        s = rs[lane]; q = rq[lane];
        #pragma unroll
        for (int off = 16; off > 0; off >>= 1) {
            s += __shfl_down_sync(0xFFFFFFFF, s, off);
            q += __shfl_down_sync(0xFFFFFFFF, q, off);
        }
        if (lane == 0) {
            float mean = s * (1.f / Dn);
            float var = q * (1.f / Dn) - mean * mean;
            stats[0] = mean;
            stats[1] = rsqrtf(var + 1e-5f);
        }
    }
    __syncthreads();
    float mean = stats[0], inv = stats[1];
    float4 gm = ((const float4*)gamma)[t];
    float4 bt = ((const float4*)beta)[t];
    float4 o;
    o.x = (rec.x - mean) * inv * gm.x + bt.x + stim.x;
    o.y = (rec.y - mean) * inv * gm.y + bt.y + stim.y;
    o.z = (rec.z - mean) * inv * gm.z + bt.z + stim.z;
    o.w = (rec.w - mean) * inv * gm.w + bt.w + stim.w;
    ((float4*)&out[row * Dn])[t] = o;
}

// ---------------------------------------------------------------------------
__global__ __launch_bounds__(256) void mlp_gemm2(
    const float* __restrict__ X, const float* __restrict__ W, int K, int N, int Kc)
{
    float* __restrict__ P = &g_mp1[0][0][0];
    const int n0 = blockIdx.x * 128;
    const int kbase = blockIdx.y * Kc;
    const int iters = Kc >> 5;

    __shared__ float Xs[32][36];
    __shared__ float Ws[32][128];
    const int tid = threadIdx.x;
    const int xrow = tid >> 3, xk = (tid & 7) << 2;
    const int wk = tid >> 5, wn = (tid & 31) << 2;
    const int tx = tid & 31, ty = tid >> 5;

    float4 xr  = *(const float4*)&X[xrow * K + kbase + xk];
    float4 wr0 = *(const float4*)&W[(size_t)(kbase + wk +  0) * N + n0 + wn];
    float4 wr1 = *(const float4*)&W[(size_t)(kbase + wk +  8) * N + n0 + wn];
    float4 wr2 = *(const float4*)&W[(size_t)(kbase + wk + 16) * N + n0 + wn];
    float4 wr3 = *(const float4*)&W[(size_t)(kbase + wk + 24) * N + n0 + wn];
    float acc[4][4] = {};

    for (int c = 0; c < iters; ++c) {
        Xs[xk + 0][xrow] = xr.x; Xs[xk + 1][xrow] = xr.y;
        Xs[xk + 2][xrow] = xr.z; Xs[xk + 3][xrow] = xr.w;
        *(float4*)&Ws[wk +  0][wn] = wr0;
        *(float4*)&Ws[wk +  8][wn] = wr1;
        *(float4*)&Ws[wk + 16][wn] = wr2;
        *(float4*)&Ws[wk + 24][wn] = wr3;
        __syncthreads();
        if (c + 1 < iters) {
            int k = kbase + (c + 1) * 32;
            xr  = *(const float4*)&X[xrow * K + k + xk];
            wr0 = *(const float4*)&W[(size_t)(k + wk +  0) * N + n0 + wn];
            wr1 = *(const float4*)&W[(size_t)(k + wk +  8) * N + n0 + wn];
            wr2 = *(const float4*)&W[(size_t)(k + wk + 16) * N + n0 + wn];
            wr3 = *(const float4*)&W[(size_t)(k + wk + 24) * N + n0 + wn];
        }
        #pragma unroll 8
        for (int kk = 0; kk < 32; ++kk) {
            float4 a = *(const float4*)&Xs[kk][ty << 2];
            float4 b = *(const float4*)&Ws[kk][tx << 2];
            acc[0][0] = fmaf(a.x, b.x, acc[0][0]); acc[0][1] = fmaf(a.x, b.y, acc[0][1]);
            acc[0][2] = fmaf(a.x, b.z, acc[0][2]); acc[0][3] = fmaf(a.x, b.w, acc[0][3]);
            acc[1][0] = fmaf(a.y, b.x, acc[1][0]); acc[1][1] = fmaf(a.y, b.y, acc[1][1]);
            acc[1][2] = fmaf(a.y, b.z, acc[1][2]); acc[1][3] = fmaf(a.y, b.w, acc[1][3]);
            acc[2][0] = fmaf(a.z, b.x, acc[2][0]); acc[2][1] = fmaf(a.z, b.y, acc[2][1]);
            acc[2][2] = fmaf(a.z, b.z, acc[2][2]); acc[2][3] = fmaf(a.z, b.w, acc[2][3]);
            acc[3][0] = fmaf(a.w, b.x, acc[3][0]); acc[3][1] = fmaf(a.w, b.y, acc[3][1]);
            acc[3][2] = fmaf(a.w, b.z, acc[3][2]); acc[3][3] = fmaf(a.w, b.w, acc[3][3]);
        }
        __syncthreads();
    }
    #pragma unroll
    for (int m = 0; m < 4; ++m) {
        int row = (ty << 2) + m;
        float4 v = make_float4(acc[m][0], acc[m][1], acc[m][2], acc[m][3]);
        *(float4*)&P[((size_t)blockIdx.y * Bn + row) * N + n0 + (tx << 2)] = v;
    }
}

// ---------------------------------------------------------------------------
__global__ __launch_bounds__(256) void lnact1(
    const float* __restrict__ bias,
    const float* __restrict__ gamma, const float* __restrict__ beta)
{
    const float* part = &g_mp1[0][0][0];
    const int row = blockIdx.x;
    __shared__ float vbuf[512];
    float s = 0.f, ss = 0.f;
    for (int i = threadIdx.x; i < 512; i += 256) {
        float v = bias[i];
        #pragma unroll 8
        for (int sp = 0; sp < 32; ++sp)
            v += part[((size_t)sp * Bn + row) * 512 + i];
        vbuf[i] = v; s += v; ss += v * v;
    }
    __shared__ float rs[256], rq[256];
    rs[threadIdx.x] = s; rq[threadIdx.x] = ss;
    __syncthreads();
    for (int off = 128; off > 0; off >>= 1) {
        if (threadIdx.x < off) {
            rs[threadIdx.x] += rs[threadIdx.x + off];
            rq[threadIdx.x] += rq[threadIdx.x + off];
        }
        __syncthreads();
    }
    float mean = rs[0] * (1.f / 512);
    float var  = rq[0] * (1.f / 512) - mean * mean;
    float inv  = rsqrtf(var + 1e-5f);
    for (int i = threadIdx.x; i < 512; i += 256) {
        float v = (vbuf[i] - mean) * inv * gamma[i] + beta[i];
        g_h1[row * 512 + i] = fmaxf(v, 0.f);
    }
}

// ---------------------------------------------------------------------------
__global__ __launch_bounds__(256) void mlp_tail(
    const float* __restrict__ fc2_w, const float* __restrict__ fc2_b,
    const float* __restrict__ ln2_g, const float* __restrict__ ln2_b,
    const float* __restrict__ fc3_w, const float* __restrict__ fc3_b,
    const float* __restrict__ lno_g, const float* __restrict__ lno_b)
{
    const int row = blockIdx.x;
    const int t = threadIdx.x;
    const int lane = t & 31, wid = t >> 5;
    __shared__ float h1s[512], h2s[256], obuf[64];
    __shared__ float rs[8], rq[8], red3[4][64], stats[2];

    for (int i = t; i < 512; i += 256) h1s[i] = g_h1[row * 512 + i];
    __syncthreads();

    float a0 = 0.f, a1 = 0.f, a2 = 0.f, a3 = 0.f;
    #pragma unroll 4
    for (int k = 0; k < 512; k += 4) {
        a0 = fmaf(h1s[k + 0], fc2_w[(k + 0) * 256 + t], a0);
        a1 = fmaf(h1s[k + 1], fc2_w[(k + 1) * 256 + t], a1);
        a2 = fmaf(h1s[k + 2], fc2_w[(k + 2) * 256 + t], a2);
        a3 = fmaf(h1s[k + 3], fc2_w[(k + 3) * 256 + t], a3);
    }
    float v = fc2_b[t] + (a0 + a1) + (a2 + a3);

    float s = v, q = v * v;
    #pragma unroll
    for (int off = 16; off > 0; off >>= 1) {
        s += __shfl_down_sync(0xFFFFFFFF, s, off);
        q += __shfl_down_sync(0xFFFFFFFF, q, off);
    }
    if (lane == 0) { rs[wid] = s; rq[wid] = q; }
    __syncthreads();
    if (t == 0) {
        float S = 0.f, Q = 0.f;
        #pragma unroll
        for (int w = 0; w < 8; ++w) { S += rs[w]; Q += rq[w]; }
        float mean = S * (1.f / 256);
        stats[0] = mean;
        stats[1] = rsqrtf(Q * (1.f / 256) - mean * mean + 1e-5f);
    }
    __syncthreads();
    h2s[t] = fmaxf((v - stats[0]) * stats[1] * ln2_g[t] + ln2_b[t], 0.f);
    __syncthreads();

    {
        int n = t & 63, sl = t >> 6;
        float p = 0.f;
        #pragma unroll 8
        for (int k = sl * 64; k < sl * 64 + 64; ++k)
            p = fmaf(h2s[k], fc3_w[k * 64 + n], p);
        red3[sl][n] = p;
    }
    __syncthreads();
    if (t < 64)
        obuf[t] = fc3_b[t] + (red3[0][t] + red3[1][t]) + (red3[2][t] + red3[3][t]);
    __syncthreads();

    float o = (t < 64) ? obuf[t] : 0.f;
    float s2 = o, q2 = o * o;
    #pragma unroll
    for (int off = 16; off > 0; off >>= 1) {
        s2 += __shfl_down_sync(0xFFFFFFFF, s2, off);
        q2 += __shfl_down_sync(0xFFFFFFFF, q2, off);
    }
    if (lane == 0 && wid < 2) { rs[wid] = s2; rq[wid] = q2; }
    __syncthreads();
    if (t == 0) {
        float S = rs[0] + rs[1], Q = rq[0] + rq[1];
        float mean = S * (1.f / 64);
        stats[0] = mean;
        stats[1] = rsqrtf(Q * (1.f / 64) - mean * mean + 1e-5f);
    }
    __syncthreads();
    if (t < 64)
        g_o[row * 64 + t] = tanhf((o - stats[0]) * stats[1] * lno_g[t] + lno_b[t]);
}

// ---------------------------------------------------------------------------
__global__ __launch_bounds__(256) void alpha_kernel()
{
    __shared__ float dsh[Un];
    int t = threadIdx.x;
    if (t < Un) {
        float s = 0.f;
        #pragma unroll
        for (int b = 0; b < Bn; b++) s += g_o[b * Un + t];
        dsh[t] = s * (9.9f / (float)Bn);
    }
    __syncthreads();
    for (int d = t; d < Dn; d += 256) g_alpha[d] = dsh[d >> 6];
}

// ---------------------------------------------------------------------------
// Pass 1: row sumsq of (W + acc*alpha) -- no V store, no dm.
// ---------------------------------------------------------------------------
__global__ __launch_bounds__(256) void norm_pass(
    const float* __restrict__ stim, const float* __restrict__ prev,
    const float* __restrict__ Wh, const float* __restrict__ Wr)
{
    const int mat = blockIdx.z;
    const float* __restrict__ A = mat ? prev : stim;
    const float* __restrict__ C = g_act[mat];
    const float* __restrict__ W = mat ? Wr : Wh;
    const int i0 = blockIdx.y * 128;
    const int j0 = blockIdx.x * 128;

    __shared__ float As[32][128];
    __shared__ float Cs[32][128];
    __shared__ float red[128][17];

    const int tid = threadIdx.x;
    #pragma unroll
    for (int r = 0; r < 4; ++r) {
        int idx = tid + r * 256;
        int b = idx >> 5, c = (idx & 31) << 2;
        *(float4*)&As[b][c] = *(const float4*)&A[b * Dn + i0 + c];
        *(float4*)&Cs[b][c] = *(const float4*)&C[b * Dn + j0 + c];
    }
    __syncthreads();

    const int tx = tid & 15, ty = tid >> 4;
    unsigned long long acc2[8][4] = {};
    #pragma unroll
    for (int b = 0; b < 32; b++) {
        float a8[8];
        *(float4*)&a8[0] = *(const float4*)&As[b][ty * 8];
        *(float4*)&a8[4] = *(const float4*)&As[b][ty * 8 + 4];
        ulonglong2 c01 = *(const ulonglong2*)&Cs[b][tx * 8];
        ulonglong2 c23 = *(const ulonglong2*)&Cs[b][tx * 8 + 4];
        #pragma unroll
        for (int m = 0; m < 8; ++m) {
            unsigned long long am;
            PACK2(am, a8[m], a8[m]);
            FMA2(acc2[m][0], am, c01.x); FMA2(acc2[m][1], am, c01.y);
            FMA2(acc2[m][2], am, c23.x); FMA2(acc2[m][3], am, c23.y);
        }
    }

    float al[8];
    *(float4*)&al[0] = *(const float4*)&g_alpha[j0 + tx * 8];
    *(float4*)&al[4] = *(const float4*)&g_alpha[j0 + tx * 8 + 4];
    #pragma unroll
    for (int m = 0; m < 8; m++) {
        int i = i0 + ty * 8 + m;
        float wv[8];
        *(float4*)&wv[0] = *(const float4*)&W[(size_t)i * Dn + j0 + tx * 8];
        *(float4*)&wv[4] = *(const float4*)&W[(size_t)i * Dn + j0 + tx * 8 + 4];
        float ac[8];
        UNPK2(ac[0], ac[1], acc2[m][0]);
        UNPK2(ac[2], ac[3], acc2[m][1]);
        UNPK2(ac[4], ac[5], acc2[m][2]);
        UNPK2(ac[6], ac[7], acc2[m][3]);
        float ssum = 0.f;
        #pragma unroll
        for (int n = 0; n < 8; n++) {
            float v = wv[n] + ac[n] * al[n];
            ssum = fmaf(v, v, ssum);
        }
        red[ty * 8 + m][tx] = ssum;
    }
    __syncthreads();
    if (tid < 128) {
        float s = 0.f;
        #pragma unroll
        for (int c = 0; c < 16; c++) s += red[tid][c];
        g_part[mat][blockIdx.x][i0 + tid] = s;
    }
}

// ---------------------------------------------------------------------------
// Pass 2: recompute V, scale by dm/max(dm*sqrt(S),1e-12), write once.
// ---------------------------------------------------------------------------
__global__ __launch_bounds__(256) void update_scale(
    const float* __restrict__ stim, const float* __restrict__ prev,
    const float* __restrict__ Wh, const float* __restrict__ Wr,
    float* __restrict__ out)
{
    const int mat = blockIdx.z;
    const float* __restrict__ A = mat ? prev : stim;
    const float* __restrict__ C = g_act[mat];
    const float* __restrict__ W = mat ? Wr : Wh;
    float* __restrict__ O = out + (size_t)(Bn + mat * Dn) * Dn;
    const int i0 = blockIdx.y * 128;
    const int j0 = blockIdx.x * 128;

    __shared__ float As[32][128];
    __shared__ float Cs[32][128];
    __shared__ float sinvs[128];

    const int tid = threadIdx.x;
    #pragma unroll
    for (int r = 0; r < 4; ++r) {
        int idx = tid + r * 256;
        int b = idx >> 5, c = (idx & 31) << 2;
        *(float4*)&As[b][c] = *(const float4*)&A[b * Dn + i0 + c];
        *(float4*)&Cs[b][c] = *(const float4*)&C[b * Dn + j0 + c];
    }
    if (tid < 128) {
        float s = 0.f;
        #pragma unroll
        for (int jb = 0; jb < 32; ++jb) s += g_part[mat][jb][i0 + tid];
        float dm = g_dm[i0 + tid];
        sinvs[tid] = dm / fmaxf(dm * sqrtf(s), 1e-12f);
    }
    __syncthreads();

    const int tx = tid & 15, ty = tid >> 4;
    unsigned long long acc2[8][4] = {};
    #pragma unroll
    for (int b = 0; b < 32; b++) {
        float a8[8];
        *(float4*)&a8[0] = *(const float4*)&As[b][ty * 8];
        *(float4*)&a8[4] = *(const float4*)&As[b][ty * 8 + 4];
        ulonglong2 c01 = *(const ulonglong2*)&Cs[b][tx * 8];
        ulonglong2 c23 = *(const ulonglong2*)&Cs[b][tx * 8 + 4];
        #pragma unroll
        for (int m = 0; m < 8; ++m) {
            unsigned long long am;
            PACK2(am, a8[m], a8[m]);
            FMA2(acc2[m][0], am, c01.x); FMA2(acc2[m][1], am, c01.y);
            FMA2(acc2[m][2], am, c23.x); FMA2(acc2[m][3], am, c23.y);
        }
    }

    float al[8];
    *(float4*)&al[0] = *(const float4*)&g_alpha[j0 + tx * 8];
    *(float4*)&al[4] = *(const float4*)&g_alpha[j0 + tx * 8 + 4];
    #pragma unroll
    for (int m = 0; m < 8; m++) {
        int i = i0 + ty * 8 + m;
        float sc = sinvs[ty * 8 + m];
        float wv[8];
        *(float4*)&wv[0] = *(const float4*)&W[(size_t)i * Dn + j0 + tx * 8];
        *(float4*)&wv[4] = *(const float4*)&W[(size_t)i * Dn + j0 + tx * 8 + 4];
        float ac[8];
        UNPK2(ac[0], ac[1], acc2[m][0]);
        UNPK2(ac[2], ac[3], acc2[m][1]);
        UNPK2(ac[4], ac[5], acc2[m][2]);
        UNPK2(ac[6], ac[7], acc2[m][3]);
        float v[8];
        #pragma unroll
        for (int n = 0; n < 8; n++)
            v[n] = (wv[n] + ac[n] * al[n]) * sc;
        *(float4*)&O[(size_t)i * Dn + j0 + tx * 8]     = *(float4*)&v[0];
        *(float4*)&O[(size_t)i * Dn + j0 + tx * 8 + 4] = *(float4*)&v[4];
    }
}

// ---------------------------------------------------------------------------
extern "C" void kernel_launch(void* const* d_in, const int* in_sizes, int n_in,
                              void* d_out, int out_size)
{
    const float* stimulus = (const float*)d_in[0];
    const float* prev_act = (const float*)d_in[1];
    const float* W_heb    = (const float*)d_in[2];
    const float* W_rec    = (const float*)d_in[3];
    const float* decay    = (const float*)d_in[4];
    const float* ln_rec_g = (const float*)d_in[5];
    const float* ln_rec_b = (const float*)d_in[6];
    const float* fc1_w    = (const float*)d_in[7];
    const float* fc1_b    = (const float*)d_in[8];
    const float* ln1_g    = (const float*)d_in[9];
    const float* ln1_b    = (const float*)d_in[10];
    const float* fc2_w    = (const float*)d_in[11];
    const float* fc2_b    = (const float*)d_in[12];
    const float* ln2_g    = (const float*)d_in[13];
    const float* ln2_b    = (const float*)d_in[14];
    const float* fc3_w    = (const float*)d_in[15];
    const float* fc3_b    = (const float*)d_in[16];
    const float* lno_g    = (const float*)d_in[17];
    const float* lno_b    = (const float*)d_in[18];
    float* out = (float*)d_out;

    prep_x1<<<512, 256>>>(stimulus, 0);                       // 1
    prep_x1<<<512, 256>>>(prev_act, 1);                       // 2
    decay_prep<<<16, 256>>>(decay);                           // 3
    fwd_mma3<<<dim3(64, 4, 2), 128>>>(W_heb, W_rec);          // 4 (ncu)
    lnfinal_fused<<<32, 1024>>>(ln_rec_g, ln_rec_b, out);     // 5
    mlp_gemm2<<<dim3(4, 32), 256>>>(out, fc1_w, 4096, 512, 128); // 6
    lnact1<<<32, 256>>>(fc1_b, ln1_g, ln1_b);                 // 7
    mlp_tail<<<32, 256>>>(fc2_w, fc2_b, ln2_g, ln2_b, fc3_w, fc3_b, lno_g, lno_b); // 8
    alpha_kernel<<<1, 256>>>();                               // 9
    norm_pass<<<dim3(32, 32, 2), 256>>>(stimulus, prev_act, W_heb, W_rec);   // 10
    update_scale<<<dim3(32, 32, 2), 256>>>(stimulus, prev_act, W_heb, W_rec, out); // 11
}